// round 2
// baseline (speedup 1.0000x reference)
#include <cuda_runtime.h>
#include <math.h>

#define NP 1024          // number of patches (N)
#define CC 4096          // channels
#define NEGV (-1e30f)

// ---------------- device scratch (no allocations allowed) ----------------
__device__ float g_cos[2u * 1024u * 1024u];   // 8 MB: masked+normalized cosine matrices
__device__ float g_norm[2][NP];               // [0]=norm(gen cols), [1]=norm(known cols)
__device__ float g_wv[2][NP][2];              // top-2 values per row
__device__ int   g_wi[2][NP][2];              // top-2 global column indices per row
__device__ float g_weights[4];                // softmax weights

// ---------------- norms: norm[n] = sum_c x[c*NP+n]^2 ----------------
// grid (32, 2), block 256: 32 n's per block, 8 c-lanes per n.
__global__ void norms_kernel(const float* __restrict__ G, const float* __restrict__ Kn) {
    const float* __restrict__ X = blockIdx.y ? Kn : G;
    const int nlocal = threadIdx.x & 31;
    const int lane8  = threadIdx.x >> 5;         // 0..7
    const int n = blockIdx.x * 32 + nlocal;
    float s = 0.f;
    #pragma unroll 8
    for (int c = lane8; c < CC; c += 8) {
        float v = X[c * NP + n];
        s += v * v;
    }
    __shared__ float sm[8][32];
    sm[lane8][nlocal] = s;
    __syncthreads();
    if (lane8 == 0) {
        float t = 0.f;
        #pragma unroll
        for (int i = 0; i < 8; i++) t += sm[i][nlocal];
        g_norm[blockIdx.y][n] = t;
    }
}

// ---------------- SGEMM with fused cosine + column-mask epilogue ----------------
// cos[z][n][m] = dot(G[:,n], B[:,m]) / sqrt(norm_g[n]*norm_B[m]); masked cols -> NEGV
// z=0: B=known, keep cols with flag==0 ; z=1: B=gen, keep cols with flag==1
// BM=BN=128, BK=16, 256 threads, 8x8 microtile, double buffered.
__global__ __launch_bounds__(256) void gemm_kernel(const float* __restrict__ G,
                                                   const float* __restrict__ Kn,
                                                   const float* __restrict__ mask) {
    const int z = blockIdx.z;
    const float* __restrict__ Bmat = z ? G : Kn;
    const int n0 = blockIdx.y * 128;
    const int m0 = blockIdx.x * 128;

    __shared__ __align__(16) float As[2][16][128];
    __shared__ __align__(16) float Bs[2][16][128];

    const int tid = threadIdx.x;
    const int tx = tid & 15, ty = tid >> 4;

    const int lin0 = tid * 4;
    const int lin1 = tid * 4 + 1024;
    const int k0 = lin0 >> 7, p0 = lin0 & 127;
    const int k1 = lin1 >> 7, p1 = lin1 & 127;

    const float* ga0 = G    + k0 * NP + n0 + p0;
    const float* ga1 = G    + k1 * NP + n0 + p1;
    const float* gb0 = Bmat + k0 * NP + m0 + p0;
    const float* gb1 = Bmat + k1 * NP + m0 + p1;

    float4 pa0 = *(const float4*)ga0;
    float4 pa1 = *(const float4*)ga1;
    float4 pb0 = *(const float4*)gb0;
    float4 pb1 = *(const float4*)gb1;

    float acc[8][8];
    #pragma unroll
    for (int i = 0; i < 8; i++)
        #pragma unroll
        for (int j = 0; j < 8; j++) acc[i][j] = 0.f;

    int buf = 0;
    *(float4*)&As[0][k0][p0] = pa0;
    *(float4*)&As[0][k1][p1] = pa1;
    *(float4*)&Bs[0][k0][p0] = pb0;
    *(float4*)&Bs[0][k1][p1] = pb1;
    __syncthreads();

    for (int kb = 1; kb < CC / 16; ++kb) {
        const int off = kb * 16 * NP;
        pa0 = *(const float4*)(ga0 + off);
        pa1 = *(const float4*)(ga1 + off);
        pb0 = *(const float4*)(gb0 + off);
        pb1 = *(const float4*)(gb1 + off);

        #pragma unroll
        for (int kk = 0; kk < 16; ++kk) {
            float a[8], b[8];
            *(float4*)&a[0] = *(const float4*)&As[buf][kk][ty * 8];
            *(float4*)&a[4] = *(const float4*)&As[buf][kk][ty * 8 + 4];
            *(float4*)&b[0] = *(const float4*)&Bs[buf][kk][tx * 8];
            *(float4*)&b[4] = *(const float4*)&Bs[buf][kk][tx * 8 + 4];
            #pragma unroll
            for (int i = 0; i < 8; i++)
                #pragma unroll
                for (int j = 0; j < 8; j++)
                    acc[i][j] += a[i] * b[j];
        }
        const int nb = buf ^ 1;
        *(float4*)&As[nb][k0][p0] = pa0;
        *(float4*)&As[nb][k1][p1] = pa1;
        *(float4*)&Bs[nb][k0][p0] = pb0;
        *(float4*)&Bs[nb][k1][p1] = pb1;
        __syncthreads();
        buf = nb;
    }
    #pragma unroll
    for (int kk = 0; kk < 16; ++kk) {
        float a[8], b[8];
        *(float4*)&a[0] = *(const float4*)&As[buf][kk][ty * 8];
        *(float4*)&a[4] = *(const float4*)&As[buf][kk][ty * 8 + 4];
        *(float4*)&b[0] = *(const float4*)&Bs[buf][kk][tx * 8];
        *(float4*)&b[4] = *(const float4*)&Bs[buf][kk][tx * 8 + 4];
        #pragma unroll
        for (int i = 0; i < 8; i++)
            #pragma unroll
            for (int j = 0; j < 8; j++)
                acc[i][j] += a[i] * b[j];
    }

    // epilogue: normalize + mask
    const float* normRow = g_norm[0];
    const float* normCol = z ? g_norm[0] : g_norm[1];
    float cn[8], keep[8];
    #pragma unroll
    for (int j = 0; j < 8; j++) {
        const int m = m0 + tx * 8 + j;
        cn[j] = normCol[m];
        const float f = mask[m];
        keep[j] = z ? f : (1.f - f);     // 1.0 => keep, 0.0 => NEGV
    }
    float* __restrict__ outp = g_cos + (size_t)z * 1048576u;
    #pragma unroll
    for (int i = 0; i < 8; i++) {
        const int n = n0 + ty * 8 + i;
        const float rn = normRow[n];
        #pragma unroll
        for (int j = 0; j < 8; j++) {
            float v = acc[i][j] * rsqrtf(rn * cn[j]);
            acc[i][j] = (keep[j] != 0.f) ? v : NEGV;
        }
        *(float4*)&outp[(size_t)n * NP + m0 + tx * 8]     = *(float4*)&acc[i][0];
        *(float4*)&outp[(size_t)n * NP + m0 + tx * 8 + 4] = *(float4*)&acc[i][4];
    }
}

// ---------------- masked top-2 per row (warp per row) ----------------
__device__ __forceinline__ void ins2(float v, int idx, float& v1, int& i1, float& v2, int& i2) {
    if (v > v1 || (v == v1 && idx < i1)) { v2 = v1; i2 = i1; v1 = v; i1 = idx; }
    else if (v > v2 || (v == v2 && idx < i2)) { v2 = v; i2 = idx; }
}

__global__ void top2_kernel() {
    const int row = blockIdx.x * 8 + (threadIdx.x >> 5);   // 0..2047
    const int z = row >> 10, n = row & 1023;
    const float* __restrict__ src = g_cos + (size_t)z * 1048576u + (size_t)n * NP;
    const int lane = threadIdx.x & 31;
    float v1 = -3.4e38f, v2 = -3.4e38f;
    int i1 = 0x7fffffff, i2 = 0x7fffffff;
    for (int m = lane; m < NP; m += 32) {
        const float v = src[m];
        if (v > v1) { v2 = v1; i2 = i1; v1 = v; i1 = m; }
        else if (v > v2) { v2 = v; i2 = m; }
    }
    for (int off = 16; off; off >>= 1) {
        float ov1 = __shfl_down_sync(0xffffffffu, v1, off);
        int   oi1 = __shfl_down_sync(0xffffffffu, i1, off);
        float ov2 = __shfl_down_sync(0xffffffffu, v2, off);
        int   oi2 = __shfl_down_sync(0xffffffffu, i2, off);
        ins2(ov1, oi1, v1, i1, v2, i2);
        ins2(ov2, oi2, v1, i1, v2, i2);
    }
    if (lane == 0) {
        g_wv[z][n][0] = v1; g_wv[z][n][1] = v2;
        g_wi[z][n][0] = i1; g_wi[z][n][1] = i2;
    }
}

// ---------------- means over masked rows + softmax ----------------
__global__ void weights_kernel(const float* __restrict__ mask) {
    const int n = threadIdx.x;   // 1024 threads
    const float f = mask[n];
    float s[5];
    s[0] = f;
    s[1] = g_wv[0][n][0] * f;
    s[2] = g_wv[0][n][1] * f;
    s[3] = g_wv[1][n][0] * f;
    s[4] = g_wv[1][n][1] * f;
    __shared__ float sm[5][32];
    const int lane = n & 31, w = n >> 5;
    #pragma unroll
    for (int k = 0; k < 5; k++) {
        float v = s[k];
        for (int off = 16; off; off >>= 1) v += __shfl_down_sync(0xffffffffu, v, off);
        if (lane == 0) sm[k][w] = v;
    }
    __syncthreads();
    if (n == 0) {
        float tot[5];
        #pragma unroll
        for (int k = 0; k < 5; k++) {
            float t = 0.f;
            for (int i = 0; i < 32; i++) t += sm[k][i];
            tot[k] = t;
        }
        const float nm = tot[0];
        float mean[4];
        #pragma unroll
        for (int j = 0; j < 4; j++) mean[j] = tot[j + 1] / nm;
        float mx = mean[0];
        #pragma unroll
        for (int j = 1; j < 4; j++) mx = fmaxf(mx, mean[j]);
        float e[4], se = 0.f;
        #pragma unroll
        for (int j = 0; j < 4; j++) { e[j] = expf(mean[j] - mx); se += e[j]; }
        #pragma unroll
        for (int j = 0; j < 4; j++) g_weights[j] = e[j] / se;
    }
}

// ---------------- gather + weighted sum into output rtn region ----------------
// block per channel c (4096), thread per patch n (1024).
__global__ void gather_kernel(const float* __restrict__ G, const float* __restrict__ Kn,
                              const float* __restrict__ mask, float* __restrict__ out) {
    const int c = blockIdx.x;
    const int n = threadIdx.x;
    const float w0 = g_weights[0], w1 = g_weights[1], w2 = g_weights[2], w3 = g_weights[3];
    const float f = mask[n];
    const float* __restrict__ kr = Kn + (size_t)c * NP;
    const float* __restrict__ gr = G  + (size_t)c * NP;
    const int a0 = g_wi[0][n][0], a1 = g_wi[0][n][1];
    const int b0 = g_wi[1][n][0], b1 = g_wi[1][n][1];
    float acc = 0.f;
    if (f == 1.0f)
        acc = w0 * kr[a0] + w1 * kr[a1] + w2 * gr[b0] + w3 * gr[b1];
    if (n == 0) {
        // spurious ind[0,0]=1 artifact: add src[0] unless this row already maps 0->0
        const float kv = kr[0], gv = gr[0];
        acc += ((f == 1.f && a0 == 0) ? 0.f : w0) * kv
             + ((f == 1.f && a1 == 0) ? 0.f : w1) * kv
             + ((f == 1.f && b0 == 0) ? 0.f : w2) * gv
             + ((f == 1.f && b1 == 0) ? 0.f : w3) * gv;
    }
    out[(size_t)(2 * CC + c) * NP + n] = acc;
}

// ---------------- launch ----------------
extern "C" void kernel_launch(void* const* d_in, const int* in_sizes, int n_in,
                              void* d_out, int out_size) {
    const float* G    = (const float*)d_in[0];   // generated (4096*1024)
    const float* Kn   = (const float*)d_in[1];   // known
    const float* mask = (const float*)d_in[2];   // 1024
    float* out = (float*)d_out;

    // passthrough copies of generated & known into output channels [0, 2C)
    cudaMemcpyAsync(out,                    G,  (size_t)CC * NP * sizeof(float),
                    cudaMemcpyDeviceToDevice, 0);
    cudaMemcpyAsync(out + (size_t)CC * NP,  Kn, (size_t)CC * NP * sizeof(float),
                    cudaMemcpyDeviceToDevice, 0);

    norms_kernel<<<dim3(32, 2), 256>>>(G, Kn);
    gemm_kernel<<<dim3(8, 8, 2), 256>>>(G, Kn, mask);
    top2_kernel<<<256, 256>>>();
    weights_kernel<<<1, 1024>>>(mask);
    gather_kernel<<<4096, 1024>>>(G, Kn, mask, out);
}

// round 5
// speedup vs baseline: 1.9181x; 1.9181x over previous
#include <cuda_runtime.h>
#include <cuda_bf16.h>
#include <math.h>
#include <stdint.h>

#define NP 1024          // patches
#define CC 4096          // channels
#define NEGV (-1e30f)

// ---------------- device scratch ----------------
__device__ float g_cos[2u * 1024u * 1024u];       // 8 MB masked+normalized cosines
__device__ float g_norm[2][NP];                   // [0]=gen, [1]=known
__device__ float g_wv[2][NP][2];
__device__ int   g_wi[2][NP][2];
__device__ float g_weights[4];
// bf16 split operands, [mat][patch n][k], K-contiguous. mat0 = generated, mat1 = known
__device__ __nv_bfloat16 g_hi[2][NP][CC];
__device__ __nv_bfloat16 g_lo[2][NP][CC];

// ==================== split fp32 -> bf16 hi/lo with transpose ====================
__global__ __launch_bounds__(256) void split_kernel(const float* __restrict__ G,
                                                    const float* __restrict__ Kn) {
    const int mat = blockIdx.z;
    const float* __restrict__ X = mat ? Kn : G;
    __shared__ float tile[32][33];
    const int n0 = blockIdx.x * 32, k0 = blockIdx.y * 32;
    const int tx = threadIdx.x & 31, ty = threadIdx.x >> 5;  // 32 x 8
    #pragma unroll
    for (int i = 0; i < 4; i++)
        tile[ty + 8 * i][tx] = X[(size_t)(k0 + ty + 8 * i) * NP + n0 + tx];
    __syncthreads();
    #pragma unroll
    for (int i = 0; i < 4; i++) {
        const int nn = ty + 8 * i;
        float v = tile[tx][nn];
        __nv_bfloat16 h = __float2bfloat16(v);
        __nv_bfloat16 l = __float2bfloat16(v - __bfloat162float(h));
        g_hi[mat][n0 + nn][k0 + tx] = h;
        g_lo[mat][n0 + nn][k0 + tx] = l;
    }
}

// ==================== norms ====================
__global__ void norms_kernel(const float* __restrict__ G, const float* __restrict__ Kn) {
    const float* __restrict__ X = blockIdx.y ? Kn : G;
    const int nlocal = threadIdx.x & 31;
    const int lane8  = threadIdx.x >> 5;
    const int n = blockIdx.x * 32 + nlocal;
    float s = 0.f;
    #pragma unroll 8
    for (int c = lane8; c < CC; c += 8) {
        float v = X[c * NP + n];
        s += v * v;
    }
    __shared__ float sm[8][32];
    sm[lane8][nlocal] = s;
    __syncthreads();
    if (lane8 == 0) {
        float t = 0.f;
        #pragma unroll
        for (int i = 0; i < 8; i++) t += sm[i][nlocal];
        g_norm[blockIdx.y][n] = t;
    }
}

// ==================== helpers ====================
__device__ __forceinline__ uint32_t s2u(const void* p) {
    uint32_t a;
    asm("{ .reg .u64 t; cvta.to.shared.u64 t, %1; cvt.u32.u64 %0, t; }" : "=r"(a) : "l"(p));
    return a;
}
#define CP16(dst, src) \
    asm volatile("cp.async.cg.shared.global [%0], [%1], 16;\n" :: "r"(dst), "l"(src))
#define CP_COMMIT() asm volatile("cp.async.commit_group;\n" ::: "memory")

// smem row layout: 64B rows (32 bf16), 4 chunks of 16B, XOR swizzle for ldmatrix
__device__ __forceinline__ uint32_t smaddr(uint32_t base, int row, int chunk) {
    return base + row * 64 + ((chunk ^ ((row >> 1) & 3)) << 4);
}

// ==================== HMMA GEMM: split-bf16, BM=BN=128, BK=32, 4 stages ====================
#define STAGES 4
#define BKC 32
#define NCHUNK 384               // 3 phases * 128 chunks of K=32
#define STAGE_BYTES 16384        // A 8KB + B 8KB
#define GEMM_SMEM (STAGES * STAGE_BYTES)   // 64 KB dynamic

__global__ __launch_bounds__(256, 1) void gemm_tc(const float* __restrict__ mask) {
    extern __shared__ __align__(1024) char dsm[];
    __shared__ float s_rrow[128], s_rcol[128], s_keep[128];

    const int tid = threadIdx.x, wid = tid >> 5, lid = tid & 31;
    const int z = blockIdx.z;
    const int n0 = blockIdx.y * 128, m0 = blockIdx.x * 128;
    const uint32_t sbase = s2u(dsm);

    const int wm = wid >> 2;       // 0..1  -> m offset wm*64
    const int wn = wid & 3;        // 0..3  -> n offset wn*32

    if (tid < 128) {
        s_rrow[tid] = rsqrtf(g_norm[0][n0 + tid]);
        const int xm = z ? 0 : 1;
        s_rcol[tid] = rsqrtf(g_norm[xm][m0 + tid]);
        const float f = mask[m0 + tid];
        s_keep[tid] = z ? f : (1.f - f);
    }

    const __nv_bfloat16* __restrict__ Ghi_ = &g_hi[0][0][0];
    const __nv_bfloat16* __restrict__ Glo_ = &g_lo[0][0][0];
    const __nv_bfloat16* __restrict__ Xhi_ = &g_hi[z ? 0 : 1][0][0];
    const __nv_bfloat16* __restrict__ Xlo_ = &g_lo[z ? 0 : 1][0][0];

    auto load_stage = [&](int st, int c) {
        const int ph = c >> 7;                 // 0:hh 1:lh 2:hl
        const int kk = (c & 127) * BKC;
        const __nv_bfloat16* __restrict__ Ap = (ph == 1) ? Glo_ : Ghi_;
        const __nv_bfloat16* __restrict__ Bp = (ph == 2) ? Xlo_ : Xhi_;
        const uint32_t sA = sbase + st * STAGE_BYTES;
        const uint32_t sB = sA + 8192;
        #pragma unroll
        for (int i = 0; i < 2; i++) {
            const int e = tid + (i << 8);
            const int r = e >> 2, cb = e & 3;
            CP16(smaddr(sA, r, cb), Ap + (size_t)(n0 + r) * CC + kk + cb * 8);
        }
        #pragma unroll
        for (int i = 0; i < 2; i++) {
            const int e = tid + (i << 8);
            const int r = e >> 2, cb = e & 3;
            CP16(smaddr(sB, r, cb), Bp + (size_t)(m0 + r) * CC + kk + cb * 8);
        }
    };

    // prologue: chunks 0..2 -> stages 0..2
    #pragma unroll
    for (int p = 0; p < STAGES - 1; p++) { load_stage(p, p); CP_COMMIT(); }

    float acc[4][4][4];
    #pragma unroll
    for (int a = 0; a < 4; a++)
        #pragma unroll
        for (int b = 0; b < 4; b++)
            #pragma unroll
            for (int d = 0; d < 4; d++) acc[a][b][d] = 0.f;

    for (int c = 0; c < NCHUNK; c++) {
        const int st = c & (STAGES - 1);
        if (c <= NCHUNK - 3)      asm volatile("cp.async.wait_group 2;\n" ::: "memory");
        else if (c == NCHUNK - 2) asm volatile("cp.async.wait_group 1;\n" ::: "memory");
        else                      asm volatile("cp.async.wait_group 0;\n" ::: "memory");
        __syncthreads();

        const uint32_t sA = sbase + st * STAGE_BYTES;
        const uint32_t sB = sA + 8192;
        #pragma unroll
        for (int ks = 0; ks < 2; ks++) {
            uint32_t af[4][4], bf[4][2];
            #pragma unroll
            for (int mi = 0; mi < 4; mi++) {
                const int row = wm * 64 + mi * 16 + (lid & 15);
                const int ch = ks * 2 + (lid >> 4);
                const uint32_t a = smaddr(sA, row, ch);
                asm volatile("ldmatrix.sync.aligned.m8n8.x4.shared.b16 {%0,%1,%2,%3}, [%4];"
                             : "=r"(af[mi][0]), "=r"(af[mi][1]), "=r"(af[mi][2]), "=r"(af[mi][3])
                             : "r"(a));
            }
            #pragma unroll
            for (int ni = 0; ni < 4; ni++) {
                const int row = wn * 32 + ni * 8 + (lid & 7);
                const int ch = ks * 2 + ((lid >> 3) & 1);
                const uint32_t a = smaddr(sB, row, ch);
                asm volatile("ldmatrix.sync.aligned.m8n8.x2.shared.b16 {%0,%1}, [%2];"
                             : "=r"(bf[ni][0]), "=r"(bf[ni][1]) : "r"(a));
            }
            #pragma unroll
            for (int mi = 0; mi < 4; mi++)
                #pragma unroll
                for (int ni = 0; ni < 4; ni++)
                    asm volatile(
                        "mma.sync.aligned.m16n8k16.row.col.f32.bf16.bf16.f32 "
                        "{%0,%1,%2,%3}, {%4,%5,%6,%7}, {%8,%9}, {%0,%1,%2,%3};"
                        : "+f"(acc[mi][ni][0]), "+f"(acc[mi][ni][1]),
                          "+f"(acc[mi][ni][2]), "+f"(acc[mi][ni][3])
                        : "r"(af[mi][0]), "r"(af[mi][1]), "r"(af[mi][2]), "r"(af[mi][3]),
                          "r"(bf[ni][0]), "r"(bf[ni][1]));
        }
        __syncthreads();

        const int nc = c + STAGES - 1;
        if (nc < NCHUNK) { load_stage(nc & (STAGES - 1), nc); CP_COMMIT(); }  // FIX: stage = nc%4
    }

    // epilogue: normalize + mask, write g_cos[z][n][m]
    const int g = lid >> 2, tc = lid & 3;
    float* __restrict__ zbase = g_cos + (size_t)z * 1048576u;
    #pragma unroll
    for (int mi = 0; mi < 4; mi++) {
        const int r0 = wm * 64 + mi * 16 + g;
        const int r1 = r0 + 8;
        const float rr0 = s_rrow[r0], rr1 = s_rrow[r1];
        float* __restrict__ p0 = zbase + (size_t)(n0 + r0) * NP + m0;
        float* __restrict__ p1 = zbase + (size_t)(n0 + r1) * NP + m0;
        #pragma unroll
        for (int ni = 0; ni < 4; ni++) {
            const int col = wn * 32 + ni * 8 + 2 * tc;
            const float rc0 = s_rcol[col], rc1 = s_rcol[col + 1];
            const bool k0 = s_keep[col] != 0.f, k1 = s_keep[col + 1] != 0.f;
            float2 o0, o1;
            o0.x = k0 ? acc[mi][ni][0] * rr0 * rc0 : NEGV;
            o0.y = k1 ? acc[mi][ni][1] * rr0 * rc1 : NEGV;
            o1.x = k0 ? acc[mi][ni][2] * rr1 * rc0 : NEGV;
            o1.y = k1 ? acc[mi][ni][3] * rr1 * rc1 : NEGV;
            *(float2*)(p0 + col) = o0;
            *(float2*)(p1 + col) = o1;
        }
    }
}

// ==================== masked top-2 per row ====================
__device__ __forceinline__ void ins2(float v, int idx, float& v1, int& i1, float& v2, int& i2) {
    if (v > v1 || (v == v1 && idx < i1)) { v2 = v1; i2 = i1; v1 = v; i1 = idx; }
    else if (v > v2 || (v == v2 && idx < i2)) { v2 = v; i2 = idx; }
}

__global__ void top2_kernel() {
    const int row = blockIdx.x * 8 + (threadIdx.x >> 5);
    const int z = row >> 10, n = row & 1023;
    const float* __restrict__ src = g_cos + (size_t)z * 1048576u + (size_t)n * NP;
    const int lane = threadIdx.x & 31;
    float v1 = -3.4e38f, v2 = -3.4e38f;
    int i1 = 0x7fffffff, i2 = 0x7fffffff;
    for (int m = lane; m < NP; m += 32) {
        const float v = src[m];
        if (v > v1) { v2 = v1; i2 = i1; v1 = v; i1 = m; }
        else if (v > v2) { v2 = v; i2 = m; }
    }
    for (int off = 16; off; off >>= 1) {
        float ov1 = __shfl_down_sync(0xffffffffu, v1, off);
        int   oi1 = __shfl_down_sync(0xffffffffu, i1, off);
        float ov2 = __shfl_down_sync(0xffffffffu, v2, off);
        int   oi2 = __shfl_down_sync(0xffffffffu, i2, off);
        ins2(ov1, oi1, v1, i1, v2, i2);
        ins2(ov2, oi2, v1, i1, v2, i2);
    }
    if (lane == 0) {
        g_wv[z][n][0] = v1; g_wv[z][n][1] = v2;
        g_wi[z][n][0] = i1; g_wi[z][n][1] = i2;
    }
}

// ==================== means + softmax ====================
__global__ void weights_kernel(const float* __restrict__ mask) {
    const int n = threadIdx.x;
    const float f = mask[n];
    float s[5];
    s[0] = f;
    s[1] = g_wv[0][n][0] * f;
    s[2] = g_wv[0][n][1] * f;
    s[3] = g_wv[1][n][0] * f;
    s[4] = g_wv[1][n][1] * f;
    __shared__ float sm[5][32];
    const int lane = n & 31, w = n >> 5;
    #pragma unroll
    for (int k = 0; k < 5; k++) {
        float v = s[k];
        for (int off = 16; off; off >>= 1) v += __shfl_down_sync(0xffffffffu, v, off);
        if (lane == 0) sm[k][w] = v;
    }
    __syncthreads();
    if (n == 0) {
        float tot[5];
        #pragma unroll
        for (int k = 0; k < 5; k++) {
            float t = 0.f;
            for (int i = 0; i < 32; i++) t += sm[k][i];
            tot[k] = t;
        }
        const float nm = tot[0];
        float mean[4];
        #pragma unroll
        for (int j = 0; j < 4; j++) mean[j] = tot[j + 1] / nm;
        float mx = mean[0];
        #pragma unroll
        for (int j = 1; j < 4; j++) mx = fmaxf(mx, mean[j]);
        float e[4], se = 0.f;
        #pragma unroll
        for (int j = 0; j < 4; j++) { e[j] = expf(mean[j] - mx); se += e[j]; }
        #pragma unroll
        for (int j = 0; j < 4; j++) g_weights[j] = e[j] / se;
    }
}

// ==================== gather ====================
__global__ void gather_kernel(const float* __restrict__ G, const float* __restrict__ Kn,
                              const float* __restrict__ mask, float* __restrict__ out) {
    const int c = blockIdx.x;
    const int n = threadIdx.x;
    const float w0 = g_weights[0], w1 = g_weights[1], w2 = g_weights[2], w3 = g_weights[3];
    const float f = mask[n];
    const float* __restrict__ kr = Kn + (size_t)c * NP;
    const float* __restrict__ gr = G  + (size_t)c * NP;
    const int a0 = g_wi[0][n][0], a1 = g_wi[0][n][1];
    const int b0 = g_wi[1][n][0], b1 = g_wi[1][n][1];
    float acc = 0.f;
    if (f == 1.0f)
        acc = w0 * kr[a0] + w1 * kr[a1] + w2 * gr[b0] + w3 * gr[b1];
    if (n == 0) {
        const float kv = kr[0], gv = gr[0];
        acc += ((f == 1.f && a0 == 0) ? 0.f : w0) * kv
             + ((f == 1.f && a1 == 0) ? 0.f : w1) * kv
             + ((f == 1.f && b0 == 0) ? 0.f : w2) * gv
             + ((f == 1.f && b1 == 0) ? 0.f : w3) * gv;
    }
    out[(size_t)(2 * CC + c) * NP + n] = acc;
}

// ==================== launch ====================
extern "C" void kernel_launch(void* const* d_in, const int* in_sizes, int n_in,
                              void* d_out, int out_size) {
    const float* G    = (const float*)d_in[0];
    const float* Kn   = (const float*)d_in[1];
    const float* mask = (const float*)d_in[2];
    float* out = (float*)d_out;

    cudaFuncSetAttribute(gemm_tc, cudaFuncAttributeMaxDynamicSharedMemorySize, GEMM_SMEM);

    cudaMemcpyAsync(out,                   G,  (size_t)CC * NP * sizeof(float),
                    cudaMemcpyDeviceToDevice, 0);
    cudaMemcpyAsync(out + (size_t)CC * NP, Kn, (size_t)CC * NP * sizeof(float),
                    cudaMemcpyDeviceToDevice, 0);

    split_kernel<<<dim3(32, 128, 2), 256>>>(G, Kn);
    norms_kernel<<<dim3(32, 2), 256>>>(G, Kn);
    gemm_tc<<<dim3(8, 8, 2), 256, GEMM_SMEM>>>(mask);
    top2_kernel<<<256, 256>>>();
    weights_kernel<<<1, 1024>>>(mask);
    gather_kernel<<<4096, 1024>>>(G, Kn, mask, out);
}

// round 6
// speedup vs baseline: 2.2861x; 1.1919x over previous
#include <cuda_runtime.h>
#include <cuda_bf16.h>
#include <math.h>
#include <stdint.h>

#define NP 1024          // patches
#define CC 4096          // channels
#define NEGV (-1e30f)

// ---------------- device scratch ----------------
__device__ float g_cos[2u * 1024u * 1024u];       // compact-row cosines
__device__ float g_norm[2][NP];                   // [0]=gen, [1]=known
__device__ float g_wv[2][NP][2];                  // zero-init; only masked rows written
__device__ int   g_wi[2][NP][2];
__device__ float g_weights[4];
__device__ int   g_nm;                            // number of masked rows
__device__ int   g_rowidx[NP];                    // compacted masked row ids (pad 0)
// bf16 split operands, [mat][patch n][k]. mat0 = generated, mat1 = known
__device__ __nv_bfloat16 g_hi[2][NP][CC];
__device__ __nv_bfloat16 g_lo[2][NP][CC];

// ==================== mask compaction ====================
__global__ void compact_kernel(const float* __restrict__ mask) {
    __shared__ int wsum[32];
    const int n = threadIdx.x;                 // 1024 threads
    const int lane = n & 31, w = n >> 5;
    const int f = (mask[n] == 1.0f) ? 1 : 0;
    const unsigned bal = __ballot_sync(0xffffffffu, f);
    const int pre = __popc(bal & ((1u << lane) - 1u));
    if (lane == 0) wsum[w] = __popc(bal);
    __syncthreads();
    if (w == 0) {
        int v = wsum[lane], orig = v;
        #pragma unroll
        for (int off = 1; off < 32; off <<= 1) {
            int t = __shfl_up_sync(0xffffffffu, v, off);
            if (lane >= off) v += t;
        }
        wsum[lane] = v - orig;                 // exclusive prefix
        if (lane == 31) g_nm = v;
    }
    __syncthreads();
    if (f) g_rowidx[wsum[w] + pre] = n;
    __syncthreads();
    if (n >= g_nm) g_rowidx[n] = 0;            // pad
}

// ==================== split fp32 -> bf16 hi/lo with transpose ====================
__global__ __launch_bounds__(256) void split_kernel(const float* __restrict__ G,
                                                    const float* __restrict__ Kn) {
    const int mat = blockIdx.z;
    const float* __restrict__ X = mat ? Kn : G;
    __shared__ float tile[32][33];
    const int n0 = blockIdx.x * 32, k0 = blockIdx.y * 32;
    const int tx = threadIdx.x & 31, ty = threadIdx.x >> 5;
    #pragma unroll
    for (int i = 0; i < 4; i++)
        tile[ty + 8 * i][tx] = X[(size_t)(k0 + ty + 8 * i) * NP + n0 + tx];
    __syncthreads();
    #pragma unroll
    for (int i = 0; i < 4; i++) {
        const int nn = ty + 8 * i;
        float v = tile[tx][nn];
        __nv_bfloat16 h = __float2bfloat16(v);
        __nv_bfloat16 l = __float2bfloat16(v - __bfloat162float(h));
        g_hi[mat][n0 + nn][k0 + tx] = h;
        g_lo[mat][n0 + nn][k0 + tx] = l;
    }
}

// ==================== norms ====================
__global__ void norms_kernel(const float* __restrict__ G, const float* __restrict__ Kn) {
    const float* __restrict__ X = blockIdx.y ? Kn : G;
    const int nlocal = threadIdx.x & 31;
    const int lane8  = threadIdx.x >> 5;
    const int n = blockIdx.x * 32 + nlocal;
    float s = 0.f;
    #pragma unroll 8
    for (int c = lane8; c < CC; c += 8) {
        float v = X[c * NP + n];
        s += v * v;
    }
    __shared__ float sm[8][32];
    sm[lane8][nlocal] = s;
    __syncthreads();
    if (lane8 == 0) {
        float t = 0.f;
        #pragma unroll
        for (int i = 0; i < 8; i++) t += sm[i][nlocal];
        g_norm[blockIdx.y][n] = t;
    }
}

// ==================== helpers ====================
__device__ __forceinline__ uint32_t s2u(const void* p) {
    uint32_t a;
    asm("{ .reg .u64 t; cvta.to.shared.u64 t, %1; cvt.u32.u64 %0, t; }" : "=r"(a) : "l"(p));
    return a;
}
#define CP16(dst, src) \
    asm volatile("cp.async.cg.shared.global [%0], [%1], 16;\n" :: "r"(dst), "l"(src))
#define CP_COMMIT() asm volatile("cp.async.commit_group;\n" ::: "memory")

// smem row layout: 64B rows (32 bf16), 4 chunks of 16B, XOR swizzle for ldmatrix
__device__ __forceinline__ uint32_t smaddr(uint32_t base, int row, int chunk) {
    return base + row * 64 + ((chunk ^ ((row >> 1) & 3)) << 4);
}

// ==================== HMMA GEMM: masked rows, BM=128, BN=64, BK=32, 4 stages ====================
#define STAGES 4
#define BKC 32
#define NCHUNK 384               // 3 phases * 128 chunks of K=32
#define A_BYTES 8192             // 128 rows * 64B
#define B_BYTES 4096             // 64 rows * 64B
#define STAGE_BYTES (A_BYTES + B_BYTES)
#define GEMM_SMEM (STAGES * STAGE_BYTES)   // 48 KB dynamic

__global__ __launch_bounds__(256) void gemm_tc(const float* __restrict__ mask) {
    const int nm = g_nm;
    const int n0 = blockIdx.y * 128;          // compact-row tile origin
    if (n0 >= nm) return;

    extern __shared__ __align__(1024) char dsm[];
    __shared__ float s_rrow[128], s_rcol[64], s_keep[64];
    __shared__ int   s_ridx[128];

    const int tid = threadIdx.x, wid = tid >> 5, lid = tid & 31;
    const int z = blockIdx.z;
    const int m0 = blockIdx.x * 64;
    const uint32_t sbase = s2u(dsm);

    const int wm = wid >> 1;       // 0..3 -> m offset wm*32
    const int wn = wid & 1;        // 0..1 -> n offset wn*32

    if (tid < 128) {
        const int orig = g_rowidx[n0 + tid];
        s_ridx[tid] = orig;
        s_rrow[tid] = rsqrtf(g_norm[0][orig]);
    }
    if (tid < 64) {
        const int xm = z ? 0 : 1;
        s_rcol[tid] = rsqrtf(g_norm[xm][m0 + tid]);
        const float f = mask[m0 + tid];
        s_keep[tid] = z ? f : (1.f - f);
    }
    __syncthreads();   // s_ridx needed by loads below

    const __nv_bfloat16* __restrict__ Ghi_ = &g_hi[0][0][0];
    const __nv_bfloat16* __restrict__ Glo_ = &g_lo[0][0][0];
    const __nv_bfloat16* __restrict__ Xhi_ = &g_hi[z ? 0 : 1][0][0];
    const __nv_bfloat16* __restrict__ Xlo_ = &g_lo[z ? 0 : 1][0][0];

    auto load_stage = [&](int st, int c) {
        const int ph = c >> 7;                 // 0:hh 1:lh 2:hl
        const int kk = (c & 127) * BKC;
        const __nv_bfloat16* __restrict__ Ap = (ph == 1) ? Glo_ : Ghi_;
        const __nv_bfloat16* __restrict__ Bp = (ph == 2) ? Xlo_ : Xhi_;
        const uint32_t sA = sbase + st * STAGE_BYTES;
        const uint32_t sB = sA + A_BYTES;
        #pragma unroll
        for (int i = 0; i < 2; i++) {          // A: 128 rows x 4 chunks = 512 ops
            const int e = tid + (i << 8);
            const int r = e >> 2, cb = e & 3;
            CP16(smaddr(sA, r, cb), Ap + (size_t)s_ridx[r] * CC + kk + cb * 8);
        }
        {                                       // B: 64 rows x 4 chunks = 256 ops
            const int r = tid >> 2, cb = tid & 3;
            CP16(smaddr(sB, r, cb), Bp + (size_t)(m0 + r) * CC + kk + cb * 8);
        }
    };

    // prologue: chunks 0..2 -> stages 0..2
    #pragma unroll
    for (int p = 0; p < STAGES - 1; p++) { load_stage(p, p); CP_COMMIT(); }

    float acc[2][4][4];
    #pragma unroll
    for (int a = 0; a < 2; a++)
        #pragma unroll
        for (int b = 0; b < 4; b++)
            #pragma unroll
            for (int d = 0; d < 4; d++) acc[a][b][d] = 0.f;

    for (int c = 0; c < NCHUNK; c++) {
        const int st = c & (STAGES - 1);
        if (c <= NCHUNK - 3)      asm volatile("cp.async.wait_group 2;\n" ::: "memory");
        else if (c == NCHUNK - 2) asm volatile("cp.async.wait_group 1;\n" ::: "memory");
        else                      asm volatile("cp.async.wait_group 0;\n" ::: "memory");
        __syncthreads();   // single sync per chunk: also protects stage reuse below

        const int nc = c + STAGES - 1;
        if (nc < NCHUNK) { load_stage(nc & (STAGES - 1), nc); CP_COMMIT(); }

        const uint32_t sA = sbase + st * STAGE_BYTES;
        const uint32_t sB = sA + A_BYTES;
        #pragma unroll
        for (int ks = 0; ks < 2; ks++) {
            uint32_t af[2][4], bf[4][2];
            #pragma unroll
            for (int mi = 0; mi < 2; mi++) {
                const int row = wm * 32 + mi * 16 + (lid & 15);
                const int ch = ks * 2 + (lid >> 4);
                asm volatile("ldmatrix.sync.aligned.m8n8.x4.shared.b16 {%0,%1,%2,%3}, [%4];"
                             : "=r"(af[mi][0]), "=r"(af[mi][1]), "=r"(af[mi][2]), "=r"(af[mi][3])
                             : "r"(smaddr(sA, row, ch)));
            }
            #pragma unroll
            for (int nip = 0; nip < 2; nip++) {
                const int row = wn * 32 + nip * 16 + ((lid >> 4) & 1) * 8 + (lid & 7);
                const int ch = ks * 2 + ((lid >> 3) & 1);
                asm volatile("ldmatrix.sync.aligned.m8n8.x4.shared.b16 {%0,%1,%2,%3}, [%4];"
                             : "=r"(bf[2 * nip][0]), "=r"(bf[2 * nip][1]),
                               "=r"(bf[2 * nip + 1][0]), "=r"(bf[2 * nip + 1][1])
                             : "r"(smaddr(sB, row, ch)));
            }
            #pragma unroll
            for (int mi = 0; mi < 2; mi++)
                #pragma unroll
                for (int ni = 0; ni < 4; ni++)
                    asm volatile(
                        "mma.sync.aligned.m16n8k16.row.col.f32.bf16.bf16.f32 "
                        "{%0,%1,%2,%3}, {%4,%5,%6,%7}, {%8,%9}, {%0,%1,%2,%3};"
                        : "+f"(acc[mi][ni][0]), "+f"(acc[mi][ni][1]),
                          "+f"(acc[mi][ni][2]), "+f"(acc[mi][ni][3])
                        : "r"(af[mi][0]), "r"(af[mi][1]), "r"(af[mi][2]), "r"(af[mi][3]),
                          "r"(bf[ni][0]), "r"(bf[ni][1]));
        }
    }

    // epilogue: normalize + mask, write g_cos[z][compact row][m]
    const int g = lid >> 2, tc = lid & 3;
    float* __restrict__ zbase = g_cos + (size_t)z * 1048576u;
    #pragma unroll
    for (int mi = 0; mi < 2; mi++) {
        const int r0 = wm * 32 + mi * 16 + g;
        const int r1 = r0 + 8;
        const float rr0 = s_rrow[r0], rr1 = s_rrow[r1];
        float* __restrict__ p0 = zbase + (size_t)(n0 + r0) * NP + m0;
        float* __restrict__ p1 = zbase + (size_t)(n0 + r1) * NP + m0;
        #pragma unroll
        for (int ni = 0; ni < 4; ni++) {
            const int col = wn * 32 + ni * 8 + 2 * tc;
            const float rc0 = s_rcol[col], rc1 = s_rcol[col + 1];
            const bool k0 = s_keep[col] != 0.f, k1 = s_keep[col + 1] != 0.f;
            float2 o0, o1;
            o0.x = k0 ? acc[mi][ni][0] * rr0 * rc0 : NEGV;
            o0.y = k1 ? acc[mi][ni][1] * rr0 * rc1 : NEGV;
            o1.x = k0 ? acc[mi][ni][2] * rr1 * rc0 : NEGV;
            o1.y = k1 ? acc[mi][ni][3] * rr1 * rc1 : NEGV;
            *(float2*)(p0 + col) = o0;
            *(float2*)(p1 + col) = o1;
        }
    }
}

// ==================== masked top-2 per compact row ====================
__device__ __forceinline__ void ins2(float v, int idx, float& v1, int& i1, float& v2, int& i2) {
    if (v > v1 || (v == v1 && idx < i1)) { v2 = v1; i2 = i1; v1 = v; i1 = idx; }
    else if (v > v2 || (v == v2 && idx < i2)) { v2 = v; i2 = idx; }
}

__global__ void top2_kernel() {
    const int row = blockIdx.x * 8 + (threadIdx.x >> 5);   // 0..2047
    const int z = row >> 10, cr = row & 1023;
    if (cr >= g_nm) return;
    const int orig = g_rowidx[cr];
    const float* __restrict__ src = g_cos + (size_t)z * 1048576u + (size_t)cr * NP;
    const int lane = threadIdx.x & 31;
    float v1 = -3.4e38f, v2 = -3.4e38f;
    int i1 = 0x7fffffff, i2 = 0x7fffffff;
    for (int m = lane; m < NP; m += 32) {
        const float v = src[m];
        if (v > v1) { v2 = v1; i2 = i1; v1 = v; i1 = m; }
        else if (v > v2) { v2 = v; i2 = m; }
    }
    for (int off = 16; off; off >>= 1) {
        float ov1 = __shfl_down_sync(0xffffffffu, v1, off);
        int   oi1 = __shfl_down_sync(0xffffffffu, i1, off);
        float ov2 = __shfl_down_sync(0xffffffffu, v2, off);
        int   oi2 = __shfl_down_sync(0xffffffffu, i2, off);
        ins2(ov1, oi1, v1, i1, v2, i2);
        ins2(ov2, oi2, v1, i1, v2, i2);
    }
    if (lane == 0) {
        g_wv[z][orig][0] = v1; g_wv[z][orig][1] = v2;
        g_wi[z][orig][0] = i1; g_wi[z][orig][1] = i2;
    }
}

// ==================== means + softmax ====================
__global__ void weights_kernel(const float* __restrict__ mask) {
    const int n = threadIdx.x;
    const float f = mask[n];
    float s[5];
    s[0] = f;
    s[1] = g_wv[0][n][0] * f;
    s[2] = g_wv[0][n][1] * f;
    s[3] = g_wv[1][n][0] * f;
    s[4] = g_wv[1][n][1] * f;
    __shared__ float sm[5][32];
    const int lane = n & 31, w = n >> 5;
    #pragma unroll
    for (int k = 0; k < 5; k++) {
        float v = s[k];
        for (int off = 16; off; off >>= 1) v += __shfl_down_sync(0xffffffffu, v, off);
        if (lane == 0) sm[k][w] = v;
    }
    __syncthreads();
    if (n == 0) {
        float tot[5];
        #pragma unroll
        for (int k = 0; k < 5; k++) {
            float t = 0.f;
            for (int i = 0; i < 32; i++) t += sm[k][i];
            tot[k] = t;
        }
        const float nm = tot[0];
        float mean[4];
        #pragma unroll
        for (int j = 0; j < 4; j++) mean[j] = tot[j + 1] / nm;
        float mx = mean[0];
        #pragma unroll
        for (int j = 1; j < 4; j++) mx = fmaxf(mx, mean[j]);
        float e[4], se = 0.f;
        #pragma unroll
        for (int j = 0; j < 4; j++) { e[j] = expf(mean[j] - mx); se += e[j]; }
        #pragma unroll
        for (int j = 0; j < 4; j++) g_weights[j] = e[j] / se;
    }
}

// ==================== gather ====================
__global__ void gather_kernel(const float* __restrict__ G, const float* __restrict__ Kn,
                              const float* __restrict__ mask, float* __restrict__ out) {
    const int c = blockIdx.x;
    const int n = threadIdx.x;
    const float w0 = g_weights[0], w1 = g_weights[1], w2 = g_weights[2], w3 = g_weights[3];
    const float f = mask[n];
    const float* __restrict__ kr = Kn + (size_t)c * NP;
    const float* __restrict__ gr = G  + (size_t)c * NP;
    const int a0 = g_wi[0][n][0], a1 = g_wi[0][n][1];
    const int b0 = g_wi[1][n][0], b1 = g_wi[1][n][1];
    float acc = 0.f;
    if (f == 1.0f)
        acc = w0 * kr[a0] + w1 * kr[a1] + w2 * gr[b0] + w3 * gr[b1];
    if (n == 0) {
        const float kv = kr[0], gv = gr[0];
        acc += ((f == 1.f && a0 == 0) ? 0.f : w0) * kv
             + ((f == 1.f && a1 == 0) ? 0.f : w1) * kv
             + ((f == 1.f && b0 == 0) ? 0.f : w2) * gv
             + ((f == 1.f && b1 == 0) ? 0.f : w3) * gv;
    }
    out[(size_t)(2 * CC + c) * NP + n] = acc;
}

// ==================== launch ====================
extern "C" void kernel_launch(void* const* d_in, const int* in_sizes, int n_in,
                              void* d_out, int out_size) {
    const float* G    = (const float*)d_in[0];
    const float* Kn   = (const float*)d_in[1];
    const float* mask = (const float*)d_in[2];
    float* out = (float*)d_out;

    cudaFuncSetAttribute(gemm_tc, cudaFuncAttributeMaxDynamicSharedMemorySize, GEMM_SMEM);

    cudaMemcpyAsync(out,                   G,  (size_t)CC * NP * sizeof(float),
                    cudaMemcpyDeviceToDevice, 0);
    cudaMemcpyAsync(out + (size_t)CC * NP, Kn, (size_t)CC * NP * sizeof(float),
                    cudaMemcpyDeviceToDevice, 0);

    compact_kernel<<<1, 1024>>>(mask);
    split_kernel<<<dim3(32, 128, 2), 256>>>(G, Kn);
    norms_kernel<<<dim3(32, 2), 256>>>(G, Kn);
    gemm_tc<<<dim3(16, 8, 2), 256, GEMM_SMEM>>>(mask);   // y blocks beyond nm exit early
    top2_kernel<<<256, 256>>>();
    weights_kernel<<<1, 1024>>>(mask);
    gather_kernel<<<4096, 1024>>>(G, Kn, mask, out);
}

// round 7
// speedup vs baseline: 3.3424x; 1.4620x over previous
#include <cuda_runtime.h>
#include <cuda_bf16.h>
#include <math.h>
#include <stdint.h>

#define NP 1024          // patches
#define CC 4096          // channels
#define NEGV (-1e30f)

// ---------------- device scratch ----------------
__device__ float g_cos[2u * 1024u * 1024u];       // split-K partial 0 (raw dot sums)
__device__ float g_part[2u * 1024u * 1024u];      // split-K partial 1
__device__ float g_norm[2][NP];                   // [0]=gen, [1]=known
__device__ float g_wv[2][NP][2];                  // zero-init; only masked rows written
__device__ int   g_wi[2][NP][2];
__device__ float g_weights[4];
__device__ int   g_nm;                            // number of masked rows
__device__ int   g_rowidx[NP];                    // compacted masked row ids (pad 0)
// bf16 split operands, [mat][patch n][k]. mat0 = generated, mat1 = known
__device__ __nv_bfloat16 g_hi[2][NP][CC];
__device__ __nv_bfloat16 g_lo[2][NP][CC];

// ==================== mask compaction ====================
__global__ void compact_kernel(const float* __restrict__ mask) {
    __shared__ int wsum[32];
    const int n = threadIdx.x;                 // 1024 threads
    const int lane = n & 31, w = n >> 5;
    const int f = (mask[n] == 1.0f) ? 1 : 0;
    const unsigned bal = __ballot_sync(0xffffffffu, f);
    const int pre = __popc(bal & ((1u << lane) - 1u));
    if (lane == 0) wsum[w] = __popc(bal);
    __syncthreads();
    if (w == 0) {
        int v = wsum[lane], orig = v;
        #pragma unroll
        for (int off = 1; off < 32; off <<= 1) {
            int t = __shfl_up_sync(0xffffffffu, v, off);
            if (lane >= off) v += t;
        }
        wsum[lane] = v - orig;                 // exclusive prefix
        if (lane == 31) g_nm = v;
    }
    __syncthreads();
    if (f) g_rowidx[wsum[w] + pre] = n;
    __syncthreads();
    if (n >= g_nm) g_rowidx[n] = 0;            // pad
}

// ==================== split fp32 -> bf16 hi/lo with transpose ====================
__global__ __launch_bounds__(256) void split_kernel(const float* __restrict__ G,
                                                    const float* __restrict__ Kn) {
    const int mat = blockIdx.z;
    const float* __restrict__ X = mat ? Kn : G;
    __shared__ float tile[32][33];
    const int n0 = blockIdx.x * 32, k0 = blockIdx.y * 32;
    const int tx = threadIdx.x & 31, ty = threadIdx.x >> 5;
    #pragma unroll
    for (int i = 0; i < 4; i++)
        tile[ty + 8 * i][tx] = X[(size_t)(k0 + ty + 8 * i) * NP + n0 + tx];
    __syncthreads();
    #pragma unroll
    for (int i = 0; i < 4; i++) {
        const int nn = ty + 8 * i;
        float v = tile[tx][nn];
        __nv_bfloat16 h = __float2bfloat16(v);
        __nv_bfloat16 l = __float2bfloat16(v - __bfloat162float(h));
        g_hi[mat][n0 + nn][k0 + tx] = h;
        g_lo[mat][n0 + nn][k0 + tx] = l;
    }
}

// ==================== norms ====================
__global__ void norms_kernel(const float* __restrict__ G, const float* __restrict__ Kn) {
    const float* __restrict__ X = blockIdx.y ? Kn : G;
    const int nlocal = threadIdx.x & 31;
    const int lane8  = threadIdx.x >> 5;
    const int n = blockIdx.x * 32 + nlocal;
    float s = 0.f;
    #pragma unroll 8
    for (int c = lane8; c < CC; c += 8) {
        float v = X[c * NP + n];
        s += v * v;
    }
    __shared__ float sm[8][32];
    sm[lane8][nlocal] = s;
    __syncthreads();
    if (lane8 == 0) {
        float t = 0.f;
        #pragma unroll
        for (int i = 0; i < 8; i++) t += sm[i][nlocal];
        g_norm[blockIdx.y][n] = t;
    }
}

// ==================== helpers ====================
__device__ __forceinline__ uint32_t s2u(const void* p) {
    uint32_t a;
    asm("{ .reg .u64 t; cvta.to.shared.u64 t, %1; cvt.u32.u64 %0, t; }" : "=r"(a) : "l"(p));
    return a;
}
#define CP16(dst, src) \
    asm volatile("cp.async.cg.shared.global [%0], [%1], 16;\n" :: "r"(dst), "l"(src))
#define CP_COMMIT() asm volatile("cp.async.commit_group;\n" ::: "memory")

__device__ __forceinline__ uint32_t smaddr(uint32_t base, int row, int chunk) {
    return base + row * 64 + ((chunk ^ ((row >> 1) & 3)) << 4);
}

// ==================== HMMA GEMM: masked rows, split-K 2-way ====================
// BM=128, BN=64, BK=32, 4 stages. blockIdx.y = rowtile*2 + kpart.
#define STAGES 4
#define BKC 32
#define NCHUNK 192               // 3 phases * 64 chunks of K=32 (2048 per kpart)
#define A_BYTES 8192             // 128 rows * 64B
#define B_BYTES 4096             // 64 rows * 64B
#define STAGE_BYTES (A_BYTES + B_BYTES)
#define GEMM_SMEM (STAGES * STAGE_BYTES)   // 48 KB dynamic

__global__ __launch_bounds__(256) void gemm_tc() {
    const int nm = g_nm;
    const int rt = blockIdx.y >> 1;
    const int kp = blockIdx.y & 1;
    const int n0 = rt * 128;                  // compact-row tile origin
    if (n0 >= nm) return;

    extern __shared__ __align__(1024) char dsm[];
    __shared__ int s_ridx[128];

    const int tid = threadIdx.x, wid = tid >> 5, lid = tid & 31;
    const int z = blockIdx.z;
    const int m0 = blockIdx.x * 64;
    const uint32_t sbase = s2u(dsm);

    const int wm = wid >> 1;       // 0..3 -> m offset wm*32
    const int wn = wid & 1;        // 0..1 -> n offset wn*32

    if (tid < 128) s_ridx[tid] = g_rowidx[n0 + tid];
    __syncthreads();

    const __nv_bfloat16* __restrict__ Ghi_ = &g_hi[0][0][0];
    const __nv_bfloat16* __restrict__ Glo_ = &g_lo[0][0][0];
    const __nv_bfloat16* __restrict__ Xhi_ = &g_hi[z ? 0 : 1][0][0];
    const __nv_bfloat16* __restrict__ Xlo_ = &g_lo[z ? 0 : 1][0][0];
    const int kbase = kp * 2048;

    auto load_stage = [&](int st, int c) {
        const int ph = c >> 6;                 // 0:hh 1:lh 2:hl
        const int kk = kbase + (c & 63) * BKC;
        const __nv_bfloat16* __restrict__ Ap = (ph == 1) ? Glo_ : Ghi_;
        const __nv_bfloat16* __restrict__ Bp = (ph == 2) ? Xlo_ : Xhi_;
        const uint32_t sA = sbase + st * STAGE_BYTES;
        const uint32_t sB = sA + A_BYTES;
        #pragma unroll
        for (int i = 0; i < 2; i++) {          // A: 128 rows x 4 chunks
            const int e = tid + (i << 8);
            const int r = e >> 2, cb = e & 3;
            CP16(smaddr(sA, r, cb), Ap + (size_t)s_ridx[r] * CC + kk + cb * 8);
        }
        {                                       // B: 64 rows x 4 chunks
            const int r = tid >> 2, cb = tid & 3;
            CP16(smaddr(sB, r, cb), Bp + (size_t)(m0 + r) * CC + kk + cb * 8);
        }
    };

    #pragma unroll
    for (int p = 0; p < STAGES - 1; p++) { load_stage(p, p); CP_COMMIT(); }

    float acc[2][4][4];
    #pragma unroll
    for (int a = 0; a < 2; a++)
        #pragma unroll
        for (int b = 0; b < 4; b++)
            #pragma unroll
            for (int d = 0; d < 4; d++) acc[a][b][d] = 0.f;

    for (int c = 0; c < NCHUNK; c++) {
        const int st = c & (STAGES - 1);
        if (c <= NCHUNK - 3)      asm volatile("cp.async.wait_group 2;\n" ::: "memory");
        else if (c == NCHUNK - 2) asm volatile("cp.async.wait_group 1;\n" ::: "memory");
        else                      asm volatile("cp.async.wait_group 0;\n" ::: "memory");
        __syncthreads();

        const int nc = c + STAGES - 1;
        if (nc < NCHUNK) { load_stage(nc & (STAGES - 1), nc); CP_COMMIT(); }

        const uint32_t sA = sbase + st * STAGE_BYTES;
        const uint32_t sB = sA + A_BYTES;
        #pragma unroll
        for (int ks = 0; ks < 2; ks++) {
            uint32_t af[2][4], bf[4][2];
            #pragma unroll
            for (int mi = 0; mi < 2; mi++) {
                const int row = wm * 32 + mi * 16 + (lid & 15);
                const int ch = ks * 2 + (lid >> 4);
                asm volatile("ldmatrix.sync.aligned.m8n8.x4.shared.b16 {%0,%1,%2,%3}, [%4];"
                             : "=r"(af[mi][0]), "=r"(af[mi][1]), "=r"(af[mi][2]), "=r"(af[mi][3])
                             : "r"(smaddr(sA, row, ch)));
            }
            #pragma unroll
            for (int nip = 0; nip < 2; nip++) {
                const int row = wn * 32 + nip * 16 + ((lid >> 4) & 1) * 8 + (lid & 7);
                const int ch = ks * 2 + ((lid >> 3) & 1);
                asm volatile("ldmatrix.sync.aligned.m8n8.x4.shared.b16 {%0,%1,%2,%3}, [%4];"
                             : "=r"(bf[2 * nip][0]), "=r"(bf[2 * nip][1]),
                               "=r"(bf[2 * nip + 1][0]), "=r"(bf[2 * nip + 1][1])
                             : "r"(smaddr(sB, row, ch)));
            }
            #pragma unroll
            for (int mi = 0; mi < 2; mi++)
                #pragma unroll
                for (int ni = 0; ni < 4; ni++)
                    asm volatile(
                        "mma.sync.aligned.m16n8k16.row.col.f32.bf16.bf16.f32 "
                        "{%0,%1,%2,%3}, {%4,%5,%6,%7}, {%8,%9}, {%0,%1,%2,%3};"
                        : "+f"(acc[mi][ni][0]), "+f"(acc[mi][ni][1]),
                          "+f"(acc[mi][ni][2]), "+f"(acc[mi][ni][3])
                        : "r"(af[mi][0]), "r"(af[mi][1]), "r"(af[mi][2]), "r"(af[mi][3]),
                          "r"(bf[ni][0]), "r"(bf[ni][1]));
        }
    }

    // epilogue: store RAW partial sums (normalize+mask folded into top2)
    const int g = lid >> 2, tc = lid & 3;
    float* __restrict__ zbase = (kp ? g_part : g_cos) + (size_t)z * 1048576u;
    #pragma unroll
    for (int mi = 0; mi < 2; mi++) {
        const int r0 = wm * 32 + mi * 16 + g;
        const int r1 = r0 + 8;
        float* __restrict__ p0 = zbase + (size_t)(n0 + r0) * NP + m0;
        float* __restrict__ p1 = zbase + (size_t)(n0 + r1) * NP + m0;
        #pragma unroll
        for (int ni = 0; ni < 4; ni++) {
            const int col = wn * 32 + ni * 8 + 2 * tc;
            float2 o0, o1;
            o0.x = acc[mi][ni][0]; o0.y = acc[mi][ni][1];
            o1.x = acc[mi][ni][2]; o1.y = acc[mi][ni][3];
            *(float2*)(p0 + col) = o0;
            *(float2*)(p1 + col) = o1;
        }
    }
}

// ==================== fused reduce + normalize + mask + top-2 ====================
__device__ __forceinline__ void ins2(float v, int idx, float& v1, int& i1, float& v2, int& i2) {
    if (v > v1 || (v == v1 && idx < i1)) { v2 = v1; i2 = i1; v1 = v; i1 = idx; }
    else if (v > v2 || (v == v2 && idx < i2)) { v2 = v; i2 = idx; }
}

__global__ void top2_kernel(const float* __restrict__ mask) {
    __shared__ float s_rcol[NP];               // keep ? rsqrt(norm) : 0 (sentinel)
    const int tid = threadIdx.x;
    const int row = blockIdx.x * 8 + (tid >> 5);   // 8 rows per block, same z
    const int z = row >> 10, cr = row & 1023;
    const int xm = z ? 0 : 1;
    for (int m = tid; m < NP; m += 256) {
        const float f = mask[m];
        const float keep = z ? f : (1.f - f);
        s_rcol[m] = (keep != 0.f) ? rsqrtf(g_norm[xm][m]) : 0.f;
    }
    __syncthreads();
    if (cr >= g_nm) return;

    const int orig = g_rowidx[cr];
    const float rn = rsqrtf(g_norm[0][orig]);
    const float* __restrict__ p0 = g_cos  + (size_t)z * 1048576u + (size_t)cr * NP;
    const float* __restrict__ p1 = g_part + (size_t)z * 1048576u + (size_t)cr * NP;
    const int lane = tid & 31;
    float v1 = -3.4e38f, v2 = -3.4e38f;
    int i1 = 0x7fffffff, i2 = 0x7fffffff;
    for (int m = lane; m < NP; m += 32) {
        const float rc = s_rcol[m];
        const float v = (rc != 0.f) ? (p0[m] + p1[m]) * rn * rc : NEGV;
        if (v > v1) { v2 = v1; i2 = i1; v1 = v; i1 = m; }
        else if (v > v2) { v2 = v; i2 = m; }
    }
    for (int off = 16; off; off >>= 1) {
        float ov1 = __shfl_down_sync(0xffffffffu, v1, off);
        int   oi1 = __shfl_down_sync(0xffffffffu, i1, off);
        float ov2 = __shfl_down_sync(0xffffffffu, v2, off);
        int   oi2 = __shfl_down_sync(0xffffffffu, i2, off);
        ins2(ov1, oi1, v1, i1, v2, i2);
        ins2(ov2, oi2, v1, i1, v2, i2);
    }
    if (lane == 0) {
        g_wv[z][orig][0] = v1; g_wv[z][orig][1] = v2;
        g_wi[z][orig][0] = i1; g_wi[z][orig][1] = i2;
    }
}

// ==================== means + softmax ====================
__global__ void weights_kernel(const float* __restrict__ mask) {
    const int n = threadIdx.x;
    const float f = mask[n];
    float s[5];
    s[0] = f;
    s[1] = g_wv[0][n][0] * f;
    s[2] = g_wv[0][n][1] * f;
    s[3] = g_wv[1][n][0] * f;
    s[4] = g_wv[1][n][1] * f;
    __shared__ float sm[5][32];
    const int lane = n & 31, w = n >> 5;
    #pragma unroll
    for (int k = 0; k < 5; k++) {
        float v = s[k];
        for (int off = 16; off; off >>= 1) v += __shfl_down_sync(0xffffffffu, v, off);
        if (lane == 0) sm[k][w] = v;
    }
    __syncthreads();
    if (n == 0) {
        float tot[5];
        #pragma unroll
        for (int k = 0; k < 5; k++) {
            float t = 0.f;
            for (int i = 0; i < 32; i++) t += sm[k][i];
            tot[k] = t;
        }
        const float nm = tot[0];
        float mean[4];
        #pragma unroll
        for (int j = 0; j < 4; j++) mean[j] = tot[j + 1] / nm;
        float mx = mean[0];
        #pragma unroll
        for (int j = 1; j < 4; j++) mx = fmaxf(mx, mean[j]);
        float e[4], se = 0.f;
        #pragma unroll
        for (int j = 0; j < 4; j++) { e[j] = expf(mean[j] - mx); se += e[j]; }
        #pragma unroll
        for (int j = 0; j < 4; j++) g_weights[j] = e[j] / se;
    }
}

// ==================== gather ====================
__global__ void gather_kernel(const float* __restrict__ G, const float* __restrict__ Kn,
                              const float* __restrict__ mask, float* __restrict__ out) {
    const int c = blockIdx.x;
    const int n = threadIdx.x;
    const float w0 = g_weights[0], w1 = g_weights[1], w2 = g_weights[2], w3 = g_weights[3];
    const float f = mask[n];
    const float* __restrict__ kr = Kn + (size_t)c * NP;
    const float* __restrict__ gr = G  + (size_t)c * NP;
    const int a0 = g_wi[0][n][0], a1 = g_wi[0][n][1];
    const int b0 = g_wi[1][n][0], b1 = g_wi[1][n][1];
    float acc = 0.f;
    if (f == 1.0f)
        acc = w0 * kr[a0] + w1 * kr[a1] + w2 * gr[b0] + w3 * gr[b1];
    if (n == 0) {
        const float kv = kr[0], gv = gr[0];
        acc += ((f == 1.f && a0 == 0) ? 0.f : w0) * kv
             + ((f == 1.f && a1 == 0) ? 0.f : w1) * kv
             + ((f == 1.f && b0 == 0) ? 0.f : w2) * gv
             + ((f == 1.f && b1 == 0) ? 0.f : w3) * gv;
    }
    out[(size_t)(2 * CC + c) * NP + n] = acc;
}

// ==================== launch ====================
extern "C" void kernel_launch(void* const* d_in, const int* in_sizes, int n_in,
                              void* d_out, int out_size) {
    const float* G    = (const float*)d_in[0];
    const float* Kn   = (const float*)d_in[1];
    const float* mask = (const float*)d_in[2];
    float* out = (float*)d_out;

    cudaFuncSetAttribute(gemm_tc, cudaFuncAttributeMaxDynamicSharedMemorySize, GEMM_SMEM);

    cudaMemcpyAsync(out,                   G,  (size_t)CC * NP * sizeof(float),
                    cudaMemcpyDeviceToDevice, 0);
    cudaMemcpyAsync(out + (size_t)CC * NP, Kn, (size_t)CC * NP * sizeof(float),
                    cudaMemcpyDeviceToDevice, 0);

    compact_kernel<<<1, 1024>>>(mask);
    split_kernel<<<dim3(32, 128, 2), 256>>>(G, Kn);
    norms_kernel<<<dim3(32, 2), 256>>>(G, Kn);
    gemm_tc<<<dim3(16, 16, 2), 256, GEMM_SMEM>>>();  // y = rowtile*2 + kpart; extras exit
    top2_kernel<<<256, 256>>>(mask);
    weights_kernel<<<1, 1024>>>(mask);
    gather_kernel<<<4096, 1024>>>(G, Kn, mask, out);
}

// round 8
// speedup vs baseline: 3.5238x; 1.0543x over previous
#include <cuda_runtime.h>
#include <cuda_bf16.h>
#include <math.h>
#include <stdint.h>

#define NP 1024          // patches
#define CC 4096          // channels
#define NEGV (-1e30f)
#define KSLICES 16       // norm partial slices (256 k each)

// ---------------- device scratch ----------------
__device__ float g_cos[2u * 1024u * 1024u];       // split-K partial 0 (raw dot sums)
__device__ float g_part[2u * 1024u * 1024u];      // partial 1
__device__ float g_part2[2u * 1024u * 1024u];     // partial 2
__device__ float g_part3[2u * 1024u * 1024u];     // partial 3
__device__ float g_normp[KSLICES][2][NP];         // norm partials per k-slice
__device__ float g_norm[2][NP];                   // [0]=gen, [1]=known
__device__ float g_wv[2][NP][2];                  // zero-init; only masked rows written
__device__ int   g_wi[2][NP][2];
__device__ float g_weights[4];
__device__ int   g_nm;
__device__ int   g_rowidx[NP];
// bf16 split operands, [mat][patch n][k]. mat0 = generated, mat1 = known
__device__ __nv_bfloat16 g_hi[2][NP][CC];
__device__ __nv_bfloat16 g_lo[2][NP][CC];

// ==================== fused split + passthrough copy + norm partials ====================
// grid (16 n-tiles, KSLICES k-slices, 2 mats), 256 threads.
// Reads X[k][n] fp32; writes passthrough to out; writes g_hi/g_lo[n][k]; norm partials.
__global__ __launch_bounds__(256) void split_kernel(const float* __restrict__ G,
                                                    const float* __restrict__ Kn,
                                                    float* __restrict__ out) {
    const int mat = blockIdx.z;
    const float* __restrict__ X = mat ? Kn : G;
    float* __restrict__ outp = out + (size_t)mat * CC * NP;
    __shared__ float tile[64][65];
    __shared__ float snorm[4][64];

    const int n0 = blockIdx.x * 64;
    const int kq0 = blockIdx.y * 256;
    const int tid = threadIdx.x;
    const int nn = tid & 63;            // phase-B: n within tile
    const int kseg = tid >> 6;          // phase-B: 0..3, 16 k's each
    float norm = 0.f;

    for (int it = 0; it < 4; ++it) {
        const int k0 = kq0 + it * 64;
        // Phase A: load 64k x 64n fp32, passthrough-store, stage to smem
        #pragma unroll
        for (int p = 0; p < 4; ++p) {
            const int r = p * 16 + (tid >> 4);
            const int c = (tid & 15) * 4;
            const size_t gi = (size_t)(k0 + r) * NP + n0 + c;
            const float4 v = *(const float4*)(X + gi);
            *(float4*)(outp + gi) = v;
            tile[r][c]     = v.x;
            tile[r][c + 1] = v.y;
            tile[r][c + 2] = v.z;
            tile[r][c + 3] = v.w;
        }
        __syncthreads();
        // Phase B: transpose-read 16 k's for one n, convert, accumulate norm
        float vv[16];
        #pragma unroll
        for (int j = 0; j < 16; ++j) {
            const float v = tile[kseg * 16 + j][nn];
            vv[j] = v;
            norm += v * v;
        }
        __nv_bfloat16 hb[16], lb[16];
        #pragma unroll
        for (int j = 0; j < 16; ++j) {
            const __nv_bfloat16 h = __float2bfloat16(vv[j]);
            hb[j] = h;
            lb[j] = __float2bfloat16(vv[j] - __bfloat162float(h));
        }
        __nv_bfloat16* __restrict__ hd = &g_hi[mat][n0 + nn][k0 + kseg * 16];
        __nv_bfloat16* __restrict__ ld = &g_lo[mat][n0 + nn][k0 + kseg * 16];
        *(uint4*)(hd)     = *(const uint4*)&hb[0];
        *(uint4*)(hd + 8) = *(const uint4*)&hb[8];
        *(uint4*)(ld)     = *(const uint4*)&lb[0];
        *(uint4*)(ld + 8) = *(const uint4*)&lb[8];
        __syncthreads();
    }
    snorm[kseg][nn] = norm;
    __syncthreads();
    if (kseg == 0)
        g_normp[blockIdx.y][mat][n0 + nn] =
            snorm[0][nn] + snorm[1][nn] + snorm[2][nn] + snorm[3][nn];
}

// ==================== mask compaction + norm combine ====================
__global__ void compact_kernel(const float* __restrict__ mask) {
    __shared__ int wsum[32];
    const int n = threadIdx.x;                 // 1024 threads
    const int lane = n & 31, w = n >> 5;
    // combine norm partials (fixed order)
    float s0 = 0.f, s1 = 0.f;
    #pragma unroll
    for (int q = 0; q < KSLICES; ++q) { s0 += g_normp[q][0][n]; s1 += g_normp[q][1][n]; }
    g_norm[0][n] = s0;
    g_norm[1][n] = s1;
    // compaction
    const int f = (mask[n] == 1.0f) ? 1 : 0;
    const unsigned bal = __ballot_sync(0xffffffffu, f);
    const int pre = __popc(bal & ((1u << lane) - 1u));
    if (lane == 0) wsum[w] = __popc(bal);
    __syncthreads();
    if (w == 0) {
        int v = wsum[lane], orig = v;
        #pragma unroll
        for (int off = 1; off < 32; off <<= 1) {
            int t = __shfl_up_sync(0xffffffffu, v, off);
            if (lane >= off) v += t;
        }
        wsum[lane] = v - orig;
        if (lane == 31) g_nm = v;
    }
    __syncthreads();
    if (f) g_rowidx[wsum[w] + pre] = n;
    __syncthreads();
    if (n >= g_nm) g_rowidx[n] = 0;
}

// ==================== helpers ====================
__device__ __forceinline__ uint32_t s2u(const void* p) {
    uint32_t a;
    asm("{ .reg .u64 t; cvta.to.shared.u64 t, %1; cvt.u32.u64 %0, t; }" : "=r"(a) : "l"(p));
    return a;
}
#define CP16(dst, src) \
    asm volatile("cp.async.cg.shared.global [%0], [%1], 16;\n" :: "r"(dst), "l"(src))
#define CP_COMMIT() asm volatile("cp.async.commit_group;\n" ::: "memory")

__device__ __forceinline__ uint32_t smaddr(uint32_t base, int row, int chunk) {
    return base + row * 64 + ((chunk ^ ((row >> 1) & 3)) << 4);
}

// ==================== HMMA GEMM: masked rows, split-K 4-way ====================
// BM=128, BN=64, BK=32, 4 stages. blockIdx.y = rowtile*4 + kpart.
#define STAGES 4
#define BKC 32
#define NCHUNK 96                // 3 phases * 32 chunks of K=32 (1024 per kpart)
#define A_BYTES 8192
#define B_BYTES 4096
#define STAGE_BYTES (A_BYTES + B_BYTES)
#define GEMM_SMEM (STAGES * STAGE_BYTES)   // 48 KB dynamic

__global__ __launch_bounds__(256) void gemm_tc() {
    const int nm = g_nm;
    const int rt = blockIdx.y >> 2;
    const int kp = blockIdx.y & 3;
    const int n0 = rt * 128;
    if (n0 >= nm) return;

    extern __shared__ __align__(1024) char dsm[];
    __shared__ int s_ridx[128];

    const int tid = threadIdx.x, wid = tid >> 5, lid = tid & 31;
    const int z = blockIdx.z;
    const int m0 = blockIdx.x * 64;
    const uint32_t sbase = s2u(dsm);

    const int wm = wid >> 1;       // 0..3 -> m offset wm*32
    const int wn = wid & 1;        // 0..1 -> n offset wn*32

    if (tid < 128) s_ridx[tid] = g_rowidx[n0 + tid];
    __syncthreads();

    const __nv_bfloat16* __restrict__ Ghi_ = &g_hi[0][0][0];
    const __nv_bfloat16* __restrict__ Glo_ = &g_lo[0][0][0];
    const __nv_bfloat16* __restrict__ Xhi_ = &g_hi[z ? 0 : 1][0][0];
    const __nv_bfloat16* __restrict__ Xlo_ = &g_lo[z ? 0 : 1][0][0];
    const int kbase = kp * 1024;

    auto load_stage = [&](int st, int c) {
        const int ph = c >> 5;                 // 0:hh 1:lh 2:hl
        const int kk = kbase + (c & 31) * BKC;
        const __nv_bfloat16* __restrict__ Ap = (ph == 1) ? Glo_ : Ghi_;
        const __nv_bfloat16* __restrict__ Bp = (ph == 2) ? Xlo_ : Xhi_;
        const uint32_t sA = sbase + st * STAGE_BYTES;
        const uint32_t sB = sA + A_BYTES;
        #pragma unroll
        for (int i = 0; i < 2; i++) {
            const int e = tid + (i << 8);
            const int r = e >> 2, cb = e & 3;
            CP16(smaddr(sA, r, cb), Ap + (size_t)s_ridx[r] * CC + kk + cb * 8);
        }
        {
            const int r = tid >> 2, cb = tid & 3;
            CP16(smaddr(sB, r, cb), Bp + (size_t)(m0 + r) * CC + kk + cb * 8);
        }
    };

    #pragma unroll
    for (int p = 0; p < STAGES - 1; p++) { load_stage(p, p); CP_COMMIT(); }

    float acc[2][4][4];
    #pragma unroll
    for (int a = 0; a < 2; a++)
        #pragma unroll
        for (int b = 0; b < 4; b++)
            #pragma unroll
            for (int d = 0; d < 4; d++) acc[a][b][d] = 0.f;

    for (int c = 0; c < NCHUNK; c++) {
        const int st = c & (STAGES - 1);
        if (c <= NCHUNK - 3)      asm volatile("cp.async.wait_group 2;\n" ::: "memory");
        else if (c == NCHUNK - 2) asm volatile("cp.async.wait_group 1;\n" ::: "memory");
        else                      asm volatile("cp.async.wait_group 0;\n" ::: "memory");
        __syncthreads();

        const int nc = c + STAGES - 1;
        if (nc < NCHUNK) { load_stage(nc & (STAGES - 1), nc); CP_COMMIT(); }

        const uint32_t sA = sbase + st * STAGE_BYTES;
        const uint32_t sB = sA + A_BYTES;
        #pragma unroll
        for (int ks = 0; ks < 2; ks++) {
            uint32_t af[2][4], bf[4][2];
            #pragma unroll
            for (int mi = 0; mi < 2; mi++) {
                const int row = wm * 32 + mi * 16 + (lid & 15);
                const int ch = ks * 2 + (lid >> 4);
                asm volatile("ldmatrix.sync.aligned.m8n8.x4.shared.b16 {%0,%1,%2,%3}, [%4];"
                             : "=r"(af[mi][0]), "=r"(af[mi][1]), "=r"(af[mi][2]), "=r"(af[mi][3])
                             : "r"(smaddr(sA, row, ch)));
            }
            #pragma unroll
            for (int nip = 0; nip < 2; nip++) {
                const int row = wn * 32 + nip * 16 + ((lid >> 4) & 1) * 8 + (lid & 7);
                const int ch = ks * 2 + ((lid >> 3) & 1);
                asm volatile("ldmatrix.sync.aligned.m8n8.x4.shared.b16 {%0,%1,%2,%3}, [%4];"
                             : "=r"(bf[2 * nip][0]), "=r"(bf[2 * nip][1]),
                               "=r"(bf[2 * nip + 1][0]), "=r"(bf[2 * nip + 1][1])
                             : "r"(smaddr(sB, row, ch)));
            }
            #pragma unroll
            for (int mi = 0; mi < 2; mi++)
                #pragma unroll
                for (int ni = 0; ni < 4; ni++)
                    asm volatile(
                        "mma.sync.aligned.m16n8k16.row.col.f32.bf16.bf16.f32 "
                        "{%0,%1,%2,%3}, {%4,%5,%6,%7}, {%8,%9}, {%0,%1,%2,%3};"
                        : "+f"(acc[mi][ni][0]), "+f"(acc[mi][ni][1]),
                          "+f"(acc[mi][ni][2]), "+f"(acc[mi][ni][3])
                        : "r"(af[mi][0]), "r"(af[mi][1]), "r"(af[mi][2]), "r"(af[mi][3]),
                          "r"(bf[ni][0]), "r"(bf[ni][1]));
        }
    }

    // epilogue: store RAW partial sums to this kpart's buffer
    const int g = lid >> 2, tc = lid & 3;
    float* __restrict__ zbase =
        ((kp == 0) ? g_cos : (kp == 1) ? g_part : (kp == 2) ? g_part2 : g_part3)
        + (size_t)z * 1048576u;
    #pragma unroll
    for (int mi = 0; mi < 2; mi++) {
        const int r0 = wm * 32 + mi * 16 + g;
        const int r1 = r0 + 8;
        float* __restrict__ p0 = zbase + (size_t)(n0 + r0) * NP + m0;
        float* __restrict__ p1 = zbase + (size_t)(n0 + r1) * NP + m0;
        #pragma unroll
        for (int ni = 0; ni < 4; ni++) {
            const int col = wn * 32 + ni * 8 + 2 * tc;
            float2 o0, o1;
            o0.x = acc[mi][ni][0]; o0.y = acc[mi][ni][1];
            o1.x = acc[mi][ni][2]; o1.y = acc[mi][ni][3];
            *(float2*)(p0 + col) = o0;
            *(float2*)(p1 + col) = o1;
        }
    }
}

// ==================== fused 4-way reduce + normalize + mask + top-2 ====================
__device__ __forceinline__ void ins2(float v, int idx, float& v1, int& i1, float& v2, int& i2) {
    if (v > v1 || (v == v1 && idx < i1)) { v2 = v1; i2 = i1; v1 = v; i1 = idx; }
    else if (v > v2 || (v == v2 && idx < i2)) { v2 = v; i2 = idx; }
}

__global__ void top2_kernel(const float* __restrict__ mask) {
    __shared__ float s_rcol[NP];               // keep ? rsqrt(norm) : 0 (sentinel)
    const int tid = threadIdx.x;
    const int row = blockIdx.x * 8 + (tid >> 5);
    const int z = row >> 10, cr = row & 1023;
    const int xm = z ? 0 : 1;
    for (int m = tid; m < NP; m += 256) {
        const float f = mask[m];
        const float keep = z ? f : (1.f - f);
        s_rcol[m] = (keep != 0.f) ? rsqrtf(g_norm[xm][m]) : 0.f;
    }
    __syncthreads();
    if (cr >= g_nm) return;

    const int orig = g_rowidx[cr];
    const float rn = rsqrtf(g_norm[0][orig]);
    const size_t off = (size_t)z * 1048576u + (size_t)cr * NP;
    const float* __restrict__ p0 = g_cos   + off;
    const float* __restrict__ p1 = g_part  + off;
    const float* __restrict__ p2 = g_part2 + off;
    const float* __restrict__ p3 = g_part3 + off;
    const int lane = tid & 31;
    float v1 = -3.4e38f, v2 = -3.4e38f;
    int i1 = 0x7fffffff, i2 = 0x7fffffff;
    for (int m = lane; m < NP; m += 32) {
        const float rc = s_rcol[m];
        const float v = (rc != 0.f) ? ((p0[m] + p1[m]) + (p2[m] + p3[m])) * rn * rc : NEGV;
        if (v > v1) { v2 = v1; i2 = i1; v1 = v; i1 = m; }
        else if (v > v2) { v2 = v; i2 = m; }
    }
    for (int off2 = 16; off2; off2 >>= 1) {
        float ov1 = __shfl_down_sync(0xffffffffu, v1, off2);
        int   oi1 = __shfl_down_sync(0xffffffffu, i1, off2);
        float ov2 = __shfl_down_sync(0xffffffffu, v2, off2);
        int   oi2 = __shfl_down_sync(0xffffffffu, i2, off2);
        ins2(ov1, oi1, v1, i1, v2, i2);
        ins2(ov2, oi2, v1, i1, v2, i2);
    }
    if (lane == 0) {
        g_wv[z][orig][0] = v1; g_wv[z][orig][1] = v2;
        g_wi[z][orig][0] = i1; g_wi[z][orig][1] = i2;
    }
}

// ==================== means + softmax ====================
__global__ void weights_kernel(const float* __restrict__ mask) {
    const int n = threadIdx.x;
    const float f = mask[n];
    float s[5];
    s[0] = f;
    s[1] = g_wv[0][n][0] * f;
    s[2] = g_wv[0][n][1] * f;
    s[3] = g_wv[1][n][0] * f;
    s[4] = g_wv[1][n][1] * f;
    __shared__ float sm[5][32];
    const int lane = n & 31, w = n >> 5;
    #pragma unroll
    for (int k = 0; k < 5; k++) {
        float v = s[k];
        for (int off = 16; off; off >>= 1) v += __shfl_down_sync(0xffffffffu, v, off);
        if (lane == 0) sm[k][w] = v;
    }
    __syncthreads();
    if (n == 0) {
        float tot[5];
        #pragma unroll
        for (int k = 0; k < 5; k++) {
            float t = 0.f;
            for (int i = 0; i < 32; i++) t += sm[k][i];
            tot[k] = t;
        }
        const float nm = tot[0];
        float mean[4];
        #pragma unroll
        for (int j = 0; j < 4; j++) mean[j] = tot[j + 1] / nm;
        float mx = mean[0];
        #pragma unroll
        for (int j = 1; j < 4; j++) mx = fmaxf(mx, mean[j]);
        float e[4], se = 0.f;
        #pragma unroll
        for (int j = 0; j < 4; j++) { e[j] = expf(mean[j] - mx); se += e[j]; }
        #pragma unroll
        for (int j = 0; j < 4; j++) g_weights[j] = e[j] / se;
    }
}

// ==================== gather ====================
__global__ void gather_kernel(const float* __restrict__ G, const float* __restrict__ Kn,
                              const float* __restrict__ mask, float* __restrict__ out) {
    const int c = blockIdx.x;
    const int n = threadIdx.x;
    const float w0 = g_weights[0], w1 = g_weights[1], w2 = g_weights[2], w3 = g_weights[3];
    const float f = mask[n];
    const float* __restrict__ kr = Kn + (size_t)c * NP;
    const float* __restrict__ gr = G  + (size_t)c * NP;
    const int a0 = g_wi[0][n][0], a1 = g_wi[0][n][1];
    const int b0 = g_wi[1][n][0], b1 = g_wi[1][n][1];
    float acc = 0.f;
    if (f == 1.0f)
        acc = w0 * kr[a0] + w1 * kr[a1] + w2 * gr[b0] + w3 * gr[b1];
    if (n == 0) {
        const float kv = kr[0], gv = gr[0];
        acc += ((f == 1.f && a0 == 0) ? 0.f : w0) * kv
             + ((f == 1.f && a1 == 0) ? 0.f : w1) * kv
             + ((f == 1.f && b0 == 0) ? 0.f : w2) * gv
             + ((f == 1.f && b1 == 0) ? 0.f : w3) * gv;
    }
    out[(size_t)(2 * CC + c) * NP + n] = acc;
}

// ==================== launch ====================
extern "C" void kernel_launch(void* const* d_in, const int* in_sizes, int n_in,
                              void* d_out, int out_size) {
    const float* G    = (const float*)d_in[0];
    const float* Kn   = (const float*)d_in[1];
    const float* mask = (const float*)d_in[2];
    float* out = (float*)d_out;

    cudaFuncSetAttribute(gemm_tc, cudaFuncAttributeMaxDynamicSharedMemorySize, GEMM_SMEM);

    split_kernel<<<dim3(16, KSLICES, 2), 256>>>(G, Kn, out);  // also passthrough + norms
    compact_kernel<<<1, 1024>>>(mask);
    gemm_tc<<<dim3(16, 32, 2), 256, GEMM_SMEM>>>();  // y = rowtile*4 + kpart
    top2_kernel<<<256, 256>>>(mask);
    weights_kernel<<<1, 1024>>>(mask);
    gather_kernel<<<4096, 1024>>>(G, Kn, mask, out);
}

// round 9
// speedup vs baseline: 5.0150x; 1.4232x over previous
#include <cuda_runtime.h>
#include <cuda_bf16.h>
#include <math.h>
#include <stdint.h>

#define NP 1024          // patches
#define CC 4096          // channels
#define NEGV (-1e30f)
#define KSLICES 16       // norm partial slices (256 k each)
#define KP 8             // split-K ways

// ---------------- device scratch ----------------
__device__ float g_par[KP][2u * 1024u * 1024u];   // raw dot partial sums [kp][z*2^20 + cr*NP + cm]
__device__ float g_normp[KSLICES][2][NP];
__device__ float g_norm[2][NP];                   // [0]=gen, [1]=known
__device__ float g_wv[2][NP][2];                  // zero-init; only masked rows written
__device__ int   g_wi[2][NP][2];
__device__ float g_weights[4];
__device__ int   g_nm;                            // masked row count
__device__ int   g_ncol[2];                       // compact col counts per z
__device__ int   g_rowidx[NP];                    // masked rows (compact -> global)
__device__ int   g_colidx[2][NP];                 // compact cols -> global (z=0: flag==0, z=1: flag==1)
// bf16 split operands, [mat][patch n][k]. mat0 = generated, mat1 = known
__device__ __nv_bfloat16 g_hi[2][NP][CC];
__device__ __nv_bfloat16 g_lo[2][NP][CC];

// ==================== fused split + passthrough copy + norm partials ====================
__global__ __launch_bounds__(256) void split_kernel(const float* __restrict__ G,
                                                    const float* __restrict__ Kn,
                                                    float* __restrict__ out) {
    const int mat = blockIdx.z;
    const float* __restrict__ X = mat ? Kn : G;
    float* __restrict__ outp = out + (size_t)mat * CC * NP;
    __shared__ float tile[64][65];
    __shared__ float snorm[4][64];

    const int n0 = blockIdx.x * 64;
    const int kq0 = blockIdx.y * 256;
    const int tid = threadIdx.x;
    const int nn = tid & 63;
    const int kseg = tid >> 6;
    float norm = 0.f;

    for (int it = 0; it < 4; ++it) {
        const int k0 = kq0 + it * 64;
        #pragma unroll
        for (int p = 0; p < 4; ++p) {
            const int r = p * 16 + (tid >> 4);
            const int c = (tid & 15) * 4;
            const size_t gi = (size_t)(k0 + r) * NP + n0 + c;
            const float4 v = *(const float4*)(X + gi);
            *(float4*)(outp + gi) = v;
            tile[r][c]     = v.x;
            tile[r][c + 1] = v.y;
            tile[r][c + 2] = v.z;
            tile[r][c + 3] = v.w;
        }
        __syncthreads();
        float vv[16];
        #pragma unroll
        for (int j = 0; j < 16; ++j) {
            const float v = tile[kseg * 16 + j][nn];
            vv[j] = v;
            norm += v * v;
        }
        __nv_bfloat16 hb[16], lb[16];
        #pragma unroll
        for (int j = 0; j < 16; ++j) {
            const __nv_bfloat16 h = __float2bfloat16(vv[j]);
            hb[j] = h;
            lb[j] = __float2bfloat16(vv[j] - __bfloat162float(h));
        }
        __nv_bfloat16* __restrict__ hd = &g_hi[mat][n0 + nn][k0 + kseg * 16];
        __nv_bfloat16* __restrict__ ld = &g_lo[mat][n0 + nn][k0 + kseg * 16];
        *(uint4*)(hd)     = *(const uint4*)&hb[0];
        *(uint4*)(hd + 8) = *(const uint4*)&hb[8];
        *(uint4*)(ld)     = *(const uint4*)&lb[0];
        *(uint4*)(ld + 8) = *(const uint4*)&lb[8];
        __syncthreads();
    }
    snorm[kseg][nn] = norm;
    __syncthreads();
    if (kseg == 0)
        g_normp[blockIdx.y][mat][n0 + nn] =
            snorm[0][nn] + snorm[1][nn] + snorm[2][nn] + snorm[3][nn];
}

// ==================== compaction (rows + cols) + norm combine ====================
__global__ void compact_kernel(const float* __restrict__ mask) {
    __shared__ int wsum1[32], wsum0[32];
    const int n = threadIdx.x;                 // 1024 threads
    const int lane = n & 31, w = n >> 5;
    float s0 = 0.f, s1 = 0.f;
    #pragma unroll
    for (int q = 0; q < KSLICES; ++q) { s0 += g_normp[q][0][n]; s1 += g_normp[q][1][n]; }
    g_norm[0][n] = s0;
    g_norm[1][n] = s1;

    const int f = (mask[n] == 1.0f) ? 1 : 0;
    const unsigned bal1 = __ballot_sync(0xffffffffu, f);
    const unsigned bal0 = ~bal1;
    const int pre1 = __popc(bal1 & ((1u << lane) - 1u));
    const int pre0 = __popc(bal0 & ((1u << lane) - 1u));
    if (lane == 0) { wsum1[w] = __popc(bal1); wsum0[w] = __popc(bal0); }
    __syncthreads();
    if (w == 0) {
        int v1 = wsum1[lane], o1 = v1;
        int v0 = wsum0[lane], o0 = v0;
        #pragma unroll
        for (int off = 1; off < 32; off <<= 1) {
            int t1 = __shfl_up_sync(0xffffffffu, v1, off);
            int t0 = __shfl_up_sync(0xffffffffu, v0, off);
            if (lane >= off) { v1 += t1; v0 += t0; }
        }
        wsum1[lane] = v1 - o1;
        wsum0[lane] = v0 - o0;
        if (lane == 31) { g_nm = v1; g_ncol[1] = v1; g_ncol[0] = v0; }
    }
    __syncthreads();
    if (f) {
        const int p = wsum1[w] + pre1;
        g_rowidx[p] = n;
        g_colidx[1][p] = n;
    } else {
        g_colidx[0][wsum0[w] + pre0] = n;
    }
    __syncthreads();
    const int nm = g_nm;
    if (n >= nm)        { g_rowidx[n] = 0; g_colidx[1][n] = 0; }
    if (n >= NP - nm)   { g_colidx[0][n] = 0; }
}

// ==================== helpers ====================
__device__ __forceinline__ uint32_t s2u(const void* p) {
    uint32_t a;
    asm("{ .reg .u64 t; cvta.to.shared.u64 t, %1; cvt.u32.u64 %0, t; }" : "=r"(a) : "l"(p));
    return a;
}
#define CP16(dst, src) \
    asm volatile("cp.async.cg.shared.global [%0], [%1], 16;\n" :: "r"(dst), "l"(src))
#define CP_COMMIT() asm volatile("cp.async.commit_group;\n" ::: "memory")

__device__ __forceinline__ uint32_t smaddr(uint32_t base, int row, int chunk) {
    return base + row * 64 + ((chunk ^ ((row >> 1) & 3)) << 4);
}

// ==================== HMMA GEMM: compact rows x compact cols, split-K 8 ====================
// BM=128, BN=64, BK=32, 4 stages. blockIdx.y = rowtile*KP + kpart.
#define STAGES 4
#define BKC 32
#define NCHUNK 48                // 3 phases * 16 chunks of K=32 (512 k per kpart)
#define A_BYTES 8192
#define B_BYTES 4096
#define STAGE_BYTES (A_BYTES + B_BYTES)
#define GEMM_SMEM (STAGES * STAGE_BYTES)   // 48 KB dynamic

__global__ __launch_bounds__(256) void gemm_tc() {
    const int z = blockIdx.z;
    const int rt = blockIdx.y >> 3;
    const int kp = blockIdx.y & 7;
    const int n0 = rt * 128;
    const int m0 = blockIdx.x * 64;
    if (n0 >= g_nm || m0 >= g_ncol[z]) return;

    extern __shared__ __align__(1024) char dsm[];
    __shared__ int s_ridx[128];
    __shared__ int s_cidx[64];

    const int tid = threadIdx.x, wid = tid >> 5, lid = tid & 31;
    const uint32_t sbase = s2u(dsm);

    const int wm = wid >> 1;       // 0..3 -> m offset wm*32
    const int wn = wid & 1;        // 0..1 -> n offset wn*32

    if (tid < 128) s_ridx[tid] = g_rowidx[n0 + tid];
    else if (tid < 192) s_cidx[tid - 128] = g_colidx[z][m0 + tid - 128];
    __syncthreads();

    const __nv_bfloat16* __restrict__ Ghi_ = &g_hi[0][0][0];
    const __nv_bfloat16* __restrict__ Glo_ = &g_lo[0][0][0];
    const __nv_bfloat16* __restrict__ Xhi_ = &g_hi[z ? 0 : 1][0][0];
    const __nv_bfloat16* __restrict__ Xlo_ = &g_lo[z ? 0 : 1][0][0];
    const int kbase = kp * 512;

    auto load_stage = [&](int st, int c) {
        const int ph = c >> 4;                 // 0:hh 1:lh 2:hl
        const int kk = kbase + (c & 15) * BKC;
        const __nv_bfloat16* __restrict__ Ap = (ph == 1) ? Glo_ : Ghi_;
        const __nv_bfloat16* __restrict__ Bp = (ph == 2) ? Xlo_ : Xhi_;
        const uint32_t sA = sbase + st * STAGE_BYTES;
        const uint32_t sB = sA + A_BYTES;
        #pragma unroll
        for (int i = 0; i < 2; i++) {
            const int e = tid + (i << 8);
            const int r = e >> 2, cb = e & 3;
            CP16(smaddr(sA, r, cb), Ap + (size_t)s_ridx[r] * CC + kk + cb * 8);
        }
        {
            const int r = tid >> 2, cb = tid & 3;
            CP16(smaddr(sB, r, cb), Bp + (size_t)s_cidx[r] * CC + kk + cb * 8);
        }
    };

    #pragma unroll
    for (int p = 0; p < STAGES - 1; p++) { load_stage(p, p); CP_COMMIT(); }

    float acc[2][4][4];
    #pragma unroll
    for (int a = 0; a < 2; a++)
        #pragma unroll
        for (int b = 0; b < 4; b++)
            #pragma unroll
            for (int d = 0; d < 4; d++) acc[a][b][d] = 0.f;

    for (int c = 0; c < NCHUNK; c++) {
        const int st = c & (STAGES - 1);
        if (c <= NCHUNK - 3)      asm volatile("cp.async.wait_group 2;\n" ::: "memory");
        else if (c == NCHUNK - 2) asm volatile("cp.async.wait_group 1;\n" ::: "memory");
        else                      asm volatile("cp.async.wait_group 0;\n" ::: "memory");
        __syncthreads();

        const int nc = c + STAGES - 1;
        if (nc < NCHUNK) { load_stage(nc & (STAGES - 1), nc); CP_COMMIT(); }

        const uint32_t sA = sbase + st * STAGE_BYTES;
        const uint32_t sB = sA + A_BYTES;
        #pragma unroll
        for (int ks = 0; ks < 2; ks++) {
            uint32_t af[2][4], bf[4][2];
            #pragma unroll
            for (int mi = 0; mi < 2; mi++) {
                const int row = wm * 32 + mi * 16 + (lid & 15);
                const int ch = ks * 2 + (lid >> 4);
                asm volatile("ldmatrix.sync.aligned.m8n8.x4.shared.b16 {%0,%1,%2,%3}, [%4];"
                             : "=r"(af[mi][0]), "=r"(af[mi][1]), "=r"(af[mi][2]), "=r"(af[mi][3])
                             : "r"(smaddr(sA, row, ch)));
            }
            #pragma unroll
            for (int nip = 0; nip < 2; nip++) {
                const int row = wn * 32 + nip * 16 + ((lid >> 4) & 1) * 8 + (lid & 7);
                const int ch = ks * 2 + ((lid >> 3) & 1);
                asm volatile("ldmatrix.sync.aligned.m8n8.x4.shared.b16 {%0,%1,%2,%3}, [%4];"
                             : "=r"(bf[2 * nip][0]), "=r"(bf[2 * nip][1]),
                               "=r"(bf[2 * nip + 1][0]), "=r"(bf[2 * nip + 1][1])
                             : "r"(smaddr(sB, row, ch)));
            }
            #pragma unroll
            for (int mi = 0; mi < 2; mi++)
                #pragma unroll
                for (int ni = 0; ni < 4; ni++)
                    asm volatile(
                        "mma.sync.aligned.m16n8k16.row.col.f32.bf16.bf16.f32 "
                        "{%0,%1,%2,%3}, {%4,%5,%6,%7}, {%8,%9}, {%0,%1,%2,%3};"
                        : "+f"(acc[mi][ni][0]), "+f"(acc[mi][ni][1]),
                          "+f"(acc[mi][ni][2]), "+f"(acc[mi][ni][3])
                        : "r"(af[mi][0]), "r"(af[mi][1]), "r"(af[mi][2]), "r"(af[mi][3]),
                          "r"(bf[ni][0]), "r"(bf[ni][1]));
        }
    }

    // epilogue: raw partial sums -> g_par[kp][z][compact row][compact col]
    const int g = lid >> 2, tc = lid & 3;
    float* __restrict__ zbase = &g_par[kp][0] + ((size_t)z << 20);
    #pragma unroll
    for (int mi = 0; mi < 2; mi++) {
        const int r0 = wm * 32 + mi * 16 + g;
        const int r1 = r0 + 8;
        float* __restrict__ p0 = zbase + (size_t)(n0 + r0) * NP + m0;
        float* __restrict__ p1 = zbase + (size_t)(n0 + r1) * NP + m0;
        #pragma unroll
        for (int ni = 0; ni < 4; ni++) {
            const int col = wn * 32 + ni * 8 + 2 * tc;
            float2 o0, o1;
            o0.x = acc[mi][ni][0]; o0.y = acc[mi][ni][1];
            o1.x = acc[mi][ni][2]; o1.y = acc[mi][ni][3];
            *(float2*)(p0 + col) = o0;
            *(float2*)(p1 + col) = o1;
        }
    }
}

// ==================== fused 8-way reduce + normalize + top-2 (compact cols) ====================
__device__ __forceinline__ void ins2(float v, int idx, float& v1, int& i1, float& v2, int& i2) {
    if (v > v1 || (v == v1 && idx < i1)) { v2 = v1; i2 = i1; v1 = v; i1 = idx; }
    else if (v > v2 || (v == v2 && idx < i2)) { v2 = v; i2 = idx; }
}

__global__ void top2_kernel() {
    __shared__ float s_rcol[NP];          // compact col -> rsqrt(norm), 0 past cnt (sentinel)
    const int tid = threadIdx.x;
    const int row = blockIdx.x * 8 + (tid >> 5);   // same z per block
    const int z = row >> 10, cr = row & 1023;
    const int xm = z ? 0 : 1;
    const int cnt = g_ncol[z];
    for (int m = tid; m < NP; m += 256)
        s_rcol[m] = (m < cnt) ? rsqrtf(g_norm[xm][g_colidx[z][m]]) : 0.f;
    __syncthreads();
    if (cr >= g_nm) return;

    const int orig = g_rowidx[cr];
    const float rn = rsqrtf(g_norm[0][orig]);
    const size_t off = ((size_t)z << 20) + (size_t)cr * NP;
    const int lane = tid & 31;
    const int cntPad = (cnt + 127) & ~127;

    float v1 = -3.4e38f, v2 = -3.4e38f;
    int i1 = 0x7fffffff, i2 = 0x7fffffff;
    for (int m = lane * 4; m < cntPad; m += 128) {
        const float4 rc = *(const float4*)&s_rcol[m];
        float4 s = *(const float4*)(&g_par[0][0] + off + m);
        #pragma unroll
        for (int q = 1; q < KP; q++) {
            const float4 a = *(const float4*)(&g_par[q][0] + off + m);
            s.x += a.x; s.y += a.y; s.z += a.z; s.w += a.w;
        }
        const float vv0 = (rc.x != 0.f) ? s.x * rn * rc.x : NEGV;
        const float vv1 = (rc.y != 0.f) ? s.y * rn * rc.y : NEGV;
        const float vv2 = (rc.z != 0.f) ? s.z * rn * rc.z : NEGV;
        const float vv3 = (rc.w != 0.f) ? s.w * rn * rc.w : NEGV;
        if (vv0 > v1) { v2 = v1; i2 = i1; v1 = vv0; i1 = m; }
        else if (vv0 > v2) { v2 = vv0; i2 = m; }
        if (vv1 > v1) { v2 = v1; i2 = i1; v1 = vv1; i1 = m + 1; }
        else if (vv1 > v2) { v2 = vv1; i2 = m + 1; }
        if (vv2 > v1) { v2 = v1; i2 = i1; v1 = vv2; i1 = m + 2; }
        else if (vv2 > v2) { v2 = vv2; i2 = m + 2; }
        if (vv3 > v1) { v2 = v1; i2 = i1; v1 = vv3; i1 = m + 3; }
        else if (vv3 > v2) { v2 = vv3; i2 = m + 3; }
    }
    for (int o = 16; o; o >>= 1) {
        float ov1 = __shfl_down_sync(0xffffffffu, v1, o);
        int   oi1 = __shfl_down_sync(0xffffffffu, i1, o);
        float ov2 = __shfl_down_sync(0xffffffffu, v2, o);
        int   oi2 = __shfl_down_sync(0xffffffffu, i2, o);
        ins2(ov1, oi1, v1, i1, v2, i2);
        ins2(ov2, oi2, v1, i1, v2, i2);
    }
    if (lane == 0) {
        g_wv[z][orig][0] = v1;
        g_wv[z][orig][1] = v2;
        g_wi[z][orig][0] = g_colidx[z][i1];     // monotone map preserves tie-break
        g_wi[z][orig][1] = g_colidx[z][i2];
    }
}

// ==================== means + softmax ====================
__global__ void weights_kernel(const float* __restrict__ mask) {
    const int n = threadIdx.x;
    const float f = mask[n];
    float s[5];
    s[0] = f;
    s[1] = g_wv[0][n][0] * f;
    s[2] = g_wv[0][n][1] * f;
    s[3] = g_wv[1][n][0] * f;
    s[4] = g_wv[1][n][1] * f;
    __shared__ float sm[5][32];
    const int lane = n & 31, w = n >> 5;
    #pragma unroll
    for (int k = 0; k < 5; k++) {
        float v = s[k];
        for (int off = 16; off; off >>= 1) v += __shfl_down_sync(0xffffffffu, v, off);
        if (lane == 0) sm[k][w] = v;
    }
    __syncthreads();
    if (n == 0) {
        float tot[5];
        #pragma unroll
        for (int k = 0; k < 5; k++) {
            float t = 0.f;
            for (int i = 0; i < 32; i++) t += sm[k][i];
            tot[k] = t;
        }
        const float nm = tot[0];
        float mean[4];
        #pragma unroll
        for (int j = 0; j < 4; j++) mean[j] = tot[j + 1] / nm;
        float mx = mean[0];
        #pragma unroll
        for (int j = 1; j < 4; j++) mx = fmaxf(mx, mean[j]);
        float e[4], se = 0.f;
        #pragma unroll
        for (int j = 0; j < 4; j++) { e[j] = expf(mean[j] - mx); se += e[j]; }
        #pragma unroll
        for (int j = 0; j < 4; j++) g_weights[j] = e[j] / se;
    }
}

// ==================== gather ====================
__global__ void gather_kernel(const float* __restrict__ G, const float* __restrict__ Kn,
                              const float* __restrict__ mask, float* __restrict__ out) {
    const int c = blockIdx.x;
    const int n = threadIdx.x;
    const float w0 = g_weights[0], w1 = g_weights[1], w2 = g_weights[2], w3 = g_weights[3];
    const float f = mask[n];
    const float* __restrict__ kr = Kn + (size_t)c * NP;
    const float* __restrict__ gr = G  + (size_t)c * NP;
    const int a0 = g_wi[0][n][0], a1 = g_wi[0][n][1];
    const int b0 = g_wi[1][n][0], b1 = g_wi[1][n][1];
    float acc = 0.f;
    if (f == 1.0f)
        acc = w0 * kr[a0] + w1 * kr[a1] + w2 * gr[b0] + w3 * gr[b1];
    if (n == 0) {
        const float kv = kr[0], gv = gr[0];
        acc += ((f == 1.f && a0 == 0) ? 0.f : w0) * kv
             + ((f == 1.f && a1 == 0) ? 0.f : w1) * kv
             + ((f == 1.f && b0 == 0) ? 0.f : w2) * gv
             + ((f == 1.f && b1 == 0) ? 0.f : w3) * gv;
    }
    out[(size_t)(2 * CC + c) * NP + n] = acc;
}

// ==================== launch ====================
extern "C" void kernel_launch(void* const* d_in, const int* in_sizes, int n_in,
                              void* d_out, int out_size) {
    const float* G    = (const float*)d_in[0];
    const float* Kn   = (const float*)d_in[1];
    const float* mask = (const float*)d_in[2];
    float* out = (float*)d_out;

    cudaFuncSetAttribute(gemm_tc, cudaFuncAttributeMaxDynamicSharedMemorySize, GEMM_SMEM);

    split_kernel<<<dim3(16, KSLICES, 2), 256>>>(G, Kn, out);  // + passthrough + norm partials
    compact_kernel<<<1, 1024>>>(mask);
    gemm_tc<<<dim3(16, 64, 2), 256, GEMM_SMEM>>>();   // y = rowtile*8 + kpart; extras exit
    top2_kernel<<<256, 256>>>();
    weights_kernel<<<1, 1024>>>(mask);
    gather_kernel<<<4096, 1024>>>(G, Kn, mask, out);
}

// round 10
// speedup vs baseline: 5.2992x; 1.0567x over previous
#include <cuda_runtime.h>
#include <cuda_bf16.h>
#include <math.h>
#include <stdint.h>

#define NP 1024          // patches
#define CC 4096          // channels
#define NEGV (-1e30f)
#define KSLICES 16       // norm partial slices (256 k each)
#define KP 8             // split-K ways

// ---------------- device scratch ----------------
__device__ float g_par[KP][2u * 1024u * 1024u];   // raw dot partial sums [kp][z*2^20 + cr*NP + cm]
__device__ float g_normp[KSLICES][2][NP];
__device__ float g_norm[2][NP];                   // [0]=gen, [1]=known
__device__ float g_wv[2][NP][2];                  // zero-init; only masked rows written
__device__ int   g_wi[2][NP][2];
__device__ float g_weights[4];
__device__ int   g_nm;                            // masked row count
__device__ int   g_ncol[2];                       // compact col counts per z
__device__ int   g_rowidx[NP];                    // masked rows (compact -> global)
__device__ int   g_colidx[2][NP];                 // compact cols -> global
// bf16 split operands, [mat][patch n][k]. mat0 = generated, mat1 = known
__device__ __nv_bfloat16 g_hi[2][NP][CC];
__device__ __nv_bfloat16 g_lo[2][NP][CC];

// ==================== fused split + passthrough copy + norm partials ====================
__global__ __launch_bounds__(256) void split_kernel(const float* __restrict__ G,
                                                    const float* __restrict__ Kn,
                                                    float* __restrict__ out) {
    const int mat = blockIdx.z;
    const float* __restrict__ X = mat ? Kn : G;
    float* __restrict__ outp = out + (size_t)mat * CC * NP;
    __shared__ float tile[64][65];
    __shared__ float snorm[4][64];

    const int n0 = blockIdx.x * 64;
    const int kq0 = blockIdx.y * 256;
    const int tid = threadIdx.x;
    const int nn = tid & 63;
    const int kseg = tid >> 6;
    float norm = 0.f;

    for (int it = 0; it < 4; ++it) {
        const int k0 = kq0 + it * 64;
        #pragma unroll
        for (int p = 0; p < 4; ++p) {
            const int r = p * 16 + (tid >> 4);
            const int c = (tid & 15) * 4;
            const size_t gi = (size_t)(k0 + r) * NP + n0 + c;
            const float4 v = *(const float4*)(X + gi);
            *(float4*)(outp + gi) = v;
            tile[r][c]     = v.x;
            tile[r][c + 1] = v.y;
            tile[r][c + 2] = v.z;
            tile[r][c + 3] = v.w;
        }
        __syncthreads();
        float vv[16];
        #pragma unroll
        for (int j = 0; j < 16; ++j) {
            const float v = tile[kseg * 16 + j][nn];
            vv[j] = v;
            norm += v * v;
        }
        __nv_bfloat16 hb[16], lb[16];
        #pragma unroll
        for (int j = 0; j < 16; ++j) {
            const __nv_bfloat16 h = __float2bfloat16(vv[j]);
            hb[j] = h;
            lb[j] = __float2bfloat16(vv[j] - __bfloat162float(h));
        }
        __nv_bfloat16* __restrict__ hd = &g_hi[mat][n0 + nn][k0 + kseg * 16];
        __nv_bfloat16* __restrict__ ld = &g_lo[mat][n0 + nn][k0 + kseg * 16];
        *(uint4*)(hd)     = *(const uint4*)&hb[0];
        *(uint4*)(hd + 8) = *(const uint4*)&hb[8];
        *(uint4*)(ld)     = *(const uint4*)&lb[0];
        *(uint4*)(ld + 8) = *(const uint4*)&lb[8];
        __syncthreads();
    }
    snorm[kseg][nn] = norm;
    __syncthreads();
    if (kseg == 0)
        g_normp[blockIdx.y][mat][n0 + nn] =
            snorm[0][nn] + snorm[1][nn] + snorm[2][nn] + snorm[3][nn];
}

// ==================== compaction (rows + cols) + norm combine ====================
__global__ void compact_kernel(const float* __restrict__ mask) {
    __shared__ int wsum1[32], wsum0[32];
    const int n = threadIdx.x;                 // 1024 threads
    const int lane = n & 31, w = n >> 5;
    float s0 = 0.f, s1 = 0.f;
    #pragma unroll
    for (int q = 0; q < KSLICES; ++q) { s0 += g_normp[q][0][n]; s1 += g_normp[q][1][n]; }
    g_norm[0][n] = s0;
    g_norm[1][n] = s1;

    const int f = (mask[n] == 1.0f) ? 1 : 0;
    const unsigned bal1 = __ballot_sync(0xffffffffu, f);
    const unsigned bal0 = ~bal1;
    const int pre1 = __popc(bal1 & ((1u << lane) - 1u));
    const int pre0 = __popc(bal0 & ((1u << lane) - 1u));
    if (lane == 0) { wsum1[w] = __popc(bal1); wsum0[w] = __popc(bal0); }
    __syncthreads();
    if (w == 0) {
        int v1 = wsum1[lane], o1 = v1;
        int v0 = wsum0[lane], o0 = v0;
        #pragma unroll
        for (int off = 1; off < 32; off <<= 1) {
            int t1 = __shfl_up_sync(0xffffffffu, v1, off);
            int t0 = __shfl_up_sync(0xffffffffu, v0, off);
            if (lane >= off) { v1 += t1; v0 += t0; }
        }
        wsum1[lane] = v1 - o1;
        wsum0[lane] = v0 - o0;
        if (lane == 31) { g_nm = v1; g_ncol[1] = v1; g_ncol[0] = v0; }
    }
    __syncthreads();
    if (f) {
        const int p = wsum1[w] + pre1;
        g_rowidx[p] = n;
        g_colidx[1][p] = n;
    } else {
        g_colidx[0][wsum0[w] + pre0] = n;
    }
    __syncthreads();
    const int nm = g_nm;
    if (n >= nm)        { g_rowidx[n] = 0; g_colidx[1][n] = 0; }
    if (n >= NP - nm)   { g_colidx[0][n] = 0; }
}

// ==================== helpers ====================
__device__ __forceinline__ uint32_t s2u(const void* p) {
    uint32_t a;
    asm("{ .reg .u64 t; cvta.to.shared.u64 t, %1; cvt.u32.u64 %0, t; }" : "=r"(a) : "l"(p));
    return a;
}
#define CP16(dst, src) \
    asm volatile("cp.async.cg.shared.global [%0], [%1], 16;\n" :: "r"(dst), "l"(src))
#define CP_COMMIT() asm volatile("cp.async.commit_group;\n" ::: "memory")

__device__ __forceinline__ uint32_t smaddr(uint32_t base, int row, int chunk) {
    return base + row * 64 + ((chunk ^ ((row >> 1) & 3)) << 4);
}

// ==================== HMMA GEMM: compact rows x compact cols, split-K 8 ====================
#define STAGES 4
#define BKC 32
#define NCHUNK 48                // 3 phases * 16 chunks of K=32 (512 k per kpart)
#define A_BYTES 8192
#define B_BYTES 4096
#define STAGE_BYTES (A_BYTES + B_BYTES)
#define GEMM_SMEM (STAGES * STAGE_BYTES)   // 48 KB dynamic

__global__ __launch_bounds__(256) void gemm_tc() {
    const int z = blockIdx.z;
    const int rt = blockIdx.y >> 3;
    const int kp = blockIdx.y & 7;
    const int n0 = rt * 128;
    const int m0 = blockIdx.x * 64;
    if (n0 >= g_nm || m0 >= g_ncol[z]) return;

    extern __shared__ __align__(1024) char dsm[];
    __shared__ int s_ridx[128];
    __shared__ int s_cidx[64];

    const int tid = threadIdx.x, wid = tid >> 5, lid = tid & 31;
    const uint32_t sbase = s2u(dsm);

    const int wm = wid >> 1;       // 0..3 -> m offset wm*32
    const int wn = wid & 1;        // 0..1 -> n offset wn*32

    if (tid < 128) s_ridx[tid] = g_rowidx[n0 + tid];
    else if (tid < 192) s_cidx[tid - 128] = g_colidx[z][m0 + tid - 128];
    __syncthreads();

    const __nv_bfloat16* __restrict__ Ghi_ = &g_hi[0][0][0];
    const __nv_bfloat16* __restrict__ Glo_ = &g_lo[0][0][0];
    const __nv_bfloat16* __restrict__ Xhi_ = &g_hi[z ? 0 : 1][0][0];
    const __nv_bfloat16* __restrict__ Xlo_ = &g_lo[z ? 0 : 1][0][0];
    const int kbase = kp * 512;

    auto load_stage = [&](int st, int c) {
        const int ph = c >> 4;                 // 0:hh 1:lh 2:hl
        const int kk = kbase + (c & 15) * BKC;
        const __nv_bfloat16* __restrict__ Ap = (ph == 1) ? Glo_ : Ghi_;
        const __nv_bfloat16* __restrict__ Bp = (ph == 2) ? Xlo_ : Xhi_;
        const uint32_t sA = sbase + st * STAGE_BYTES;
        const uint32_t sB = sA + A_BYTES;
        #pragma unroll
        for (int i = 0; i < 2; i++) {
            const int e = tid + (i << 8);
            const int r = e >> 2, cb = e & 3;
            CP16(smaddr(sA, r, cb), Ap + (size_t)s_ridx[r] * CC + kk + cb * 8);
        }
        {
            const int r = tid >> 2, cb = tid & 3;
            CP16(smaddr(sB, r, cb), Bp + (size_t)s_cidx[r] * CC + kk + cb * 8);
        }
    };

    #pragma unroll
    for (int p = 0; p < STAGES - 1; p++) { load_stage(p, p); CP_COMMIT(); }

    float acc[2][4][4];
    #pragma unroll
    for (int a = 0; a < 2; a++)
        #pragma unroll
        for (int b = 0; b < 4; b++)
            #pragma unroll
            for (int d = 0; d < 4; d++) acc[a][b][d] = 0.f;

    for (int c = 0; c < NCHUNK; c++) {
        const int st = c & (STAGES - 1);
        if (c <= NCHUNK - 3)      asm volatile("cp.async.wait_group 2;\n" ::: "memory");
        else if (c == NCHUNK - 2) asm volatile("cp.async.wait_group 1;\n" ::: "memory");
        else                      asm volatile("cp.async.wait_group 0;\n" ::: "memory");
        __syncthreads();

        const int nc = c + STAGES - 1;
        if (nc < NCHUNK) { load_stage(nc & (STAGES - 1), nc); CP_COMMIT(); }

        const uint32_t sA = sbase + st * STAGE_BYTES;
        const uint32_t sB = sA + A_BYTES;
        #pragma unroll
        for (int ks = 0; ks < 2; ks++) {
            uint32_t af[2][4], bf[4][2];
            #pragma unroll
            for (int mi = 0; mi < 2; mi++) {
                const int row = wm * 32 + mi * 16 + (lid & 15);
                const int ch = ks * 2 + (lid >> 4);
                asm volatile("ldmatrix.sync.aligned.m8n8.x4.shared.b16 {%0,%1,%2,%3}, [%4];"
                             : "=r"(af[mi][0]), "=r"(af[mi][1]), "=r"(af[mi][2]), "=r"(af[mi][3])
                             : "r"(smaddr(sA, row, ch)));
            }
            #pragma unroll
            for (int nip = 0; nip < 2; nip++) {
                const int row = wn * 32 + nip * 16 + ((lid >> 4) & 1) * 8 + (lid & 7);
                const int ch = ks * 2 + ((lid >> 3) & 1);
                asm volatile("ldmatrix.sync.aligned.m8n8.x4.shared.b16 {%0,%1,%2,%3}, [%4];"
                             : "=r"(bf[2 * nip][0]), "=r"(bf[2 * nip][1]),
                               "=r"(bf[2 * nip + 1][0]), "=r"(bf[2 * nip + 1][1])
                             : "r"(smaddr(sB, row, ch)));
            }
            #pragma unroll
            for (int mi = 0; mi < 2; mi++)
                #pragma unroll
                for (int ni = 0; ni < 4; ni++)
                    asm volatile(
                        "mma.sync.aligned.m16n8k16.row.col.f32.bf16.bf16.f32 "
                        "{%0,%1,%2,%3}, {%4,%5,%6,%7}, {%8,%9}, {%0,%1,%2,%3};"
                        : "+f"(acc[mi][ni][0]), "+f"(acc[mi][ni][1]),
                          "+f"(acc[mi][ni][2]), "+f"(acc[mi][ni][3])
                        : "r"(af[mi][0]), "r"(af[mi][1]), "r"(af[mi][2]), "r"(af[mi][3]),
                          "r"(bf[ni][0]), "r"(bf[ni][1]));
        }
    }

    // epilogue: raw partial sums -> g_par[kp][z][compact row][compact col]
    const int g = lid >> 2, tc = lid & 3;
    float* __restrict__ zbase = &g_par[kp][0] + ((size_t)z << 20);
    #pragma unroll
    for (int mi = 0; mi < 2; mi++) {
        const int r0 = wm * 32 + mi * 16 + g;
        const int r1 = r0 + 8;
        float* __restrict__ p0 = zbase + (size_t)(n0 + r0) * NP + m0;
        float* __restrict__ p1 = zbase + (size_t)(n0 + r1) * NP + m0;
        #pragma unroll
        for (int ni = 0; ni < 4; ni++) {
            const int col = wn * 32 + ni * 8 + 2 * tc;
            float2 o0, o1;
            o0.x = acc[mi][ni][0]; o0.y = acc[mi][ni][1];
            o1.x = acc[mi][ni][2]; o1.y = acc[mi][ni][3];
            *(float2*)(p0 + col) = o0;
            *(float2*)(p1 + col) = o1;
        }
    }
}

// ==================== block-per-row 8-way reduce + normalize + top-2 ====================
__device__ __forceinline__ void ins2(float v, int idx, float& v1, int& i1, float& v2, int& i2) {
    if (v > v1 || (v == v1 && idx < i1)) { v2 = v1; i2 = i1; v1 = v; i1 = idx; }
    else if (v > v2 || (v == v2 && idx < i2)) { v2 = v; i2 = idx; }
}

__global__ __launch_bounds__(256) void top2_kernel() {
    const int bid = blockIdx.x;
    const int z = bid >> 10, cr = bid & 1023;
    if (cr >= g_nm) return;
    const int cnt = g_ncol[z];
    const int tid = threadIdx.x, lane = tid & 31, wid = tid >> 5;
    const int xm = z ? 0 : 1;
    const int orig = g_rowidx[cr];
    const float rn = rsqrtf(g_norm[0][orig]);
    const size_t off = ((size_t)z << 20) + (size_t)cr * NP;

    float v1 = -3.4e38f, v2 = -3.4e38f;
    int i1 = 0x7fffffff, i2 = 0x7fffffff;
    const int m = tid * 4;                      // 256 threads cover 1024 cols
    if (m < cnt) {
        float4 s = *(const float4*)(&g_par[0][0] + off + m);
        #pragma unroll
        for (int q = 1; q < KP; q++) {
            const float4 a = *(const float4*)(&g_par[q][0] + off + m);
            s.x += a.x; s.y += a.y; s.z += a.z; s.w += a.w;
        }
        float sv[4] = {s.x, s.y, s.z, s.w};
        #pragma unroll
        for (int j = 0; j < 4; j++) {
            float v = NEGV;
            if (m + j < cnt) {
                const float rc = rsqrtf(g_norm[xm][g_colidx[z][m + j]]);
                v = sv[j] * rn * rc;
            }
            if (v > v1) { v2 = v1; i2 = i1; v1 = v; i1 = m + j; }
            else if (v > v2) { v2 = v; i2 = m + j; }
        }
    }
    // warp reduce
    for (int o = 16; o; o >>= 1) {
        float ov1 = __shfl_down_sync(0xffffffffu, v1, o);
        int   oi1 = __shfl_down_sync(0xffffffffu, i1, o);
        float ov2 = __shfl_down_sync(0xffffffffu, v2, o);
        int   oi2 = __shfl_down_sync(0xffffffffu, i2, o);
        ins2(ov1, oi1, v1, i1, v2, i2);
        ins2(ov2, oi2, v1, i1, v2, i2);
    }
    __shared__ float sv1[8], sv2[8];
    __shared__ int   si1[8], si2[8];
    if (lane == 0) { sv1[wid] = v1; si1[wid] = i1; sv2[wid] = v2; si2[wid] = i2; }
    __syncthreads();
    if (wid == 0) {
        if (lane < 8) { v1 = sv1[lane]; i1 = si1[lane]; v2 = sv2[lane]; i2 = si2[lane]; }
        else { v1 = v2 = -3.4e38f; i1 = i2 = 0x7fffffff; }
        for (int o = 4; o; o >>= 1) {
            float ov1 = __shfl_down_sync(0xffffffffu, v1, o);
            int   oi1 = __shfl_down_sync(0xffffffffu, i1, o);
            float ov2 = __shfl_down_sync(0xffffffffu, v2, o);
            int   oi2 = __shfl_down_sync(0xffffffffu, i2, o);
            ins2(ov1, oi1, v1, i1, v2, i2);
            ins2(ov2, oi2, v1, i1, v2, i2);
        }
        if (lane == 0) {
            g_wv[z][orig][0] = v1;
            g_wv[z][orig][1] = v2;
            g_wi[z][orig][0] = g_colidx[z][i1];   // monotone map preserves tie-break
            g_wi[z][orig][1] = g_colidx[z][i2];
        }
    }
}

// ==================== means + softmax ====================
__global__ void weights_kernel(const float* __restrict__ mask) {
    const int n = threadIdx.x;
    const float f = mask[n];
    float s[5];
    s[0] = f;
    s[1] = g_wv[0][n][0] * f;
    s[2] = g_wv[0][n][1] * f;
    s[3] = g_wv[1][n][0] * f;
    s[4] = g_wv[1][n][1] * f;
    __shared__ float sm[5][32];
    const int lane = n & 31, w = n >> 5;
    #pragma unroll
    for (int k = 0; k < 5; k++) {
        float v = s[k];
        for (int off = 16; off; off >>= 1) v += __shfl_down_sync(0xffffffffu, v, off);
        if (lane == 0) sm[k][w] = v;
    }
    __syncthreads();
    if (n == 0) {
        float tot[5];
        #pragma unroll
        for (int k = 0; k < 5; k++) {
            float t = 0.f;
            for (int i = 0; i < 32; i++) t += sm[k][i];
            tot[k] = t;
        }
        const float nm = tot[0];
        float mean[4];
        #pragma unroll
        for (int j = 0; j < 4; j++) mean[j] = tot[j + 1] / nm;
        float mx = mean[0];
        #pragma unroll
        for (int j = 1; j < 4; j++) mx = fmaxf(mx, mean[j]);
        float e[4], se = 0.f;
        #pragma unroll
        for (int j = 0; j < 4; j++) { e[j] = expf(mean[j] - mx); se += e[j]; }
        #pragma unroll
        for (int j = 0; j < 4; j++) g_weights[j] = e[j] / se;
    }
}

// ==================== gather ====================
__global__ void gather_kernel(const float* __restrict__ G, const float* __restrict__ Kn,
                              const float* __restrict__ mask, float* __restrict__ out) {
    const int c = blockIdx.x;
    const int n = threadIdx.x;
    const float w0 = g_weights[0], w1 = g_weights[1], w2 = g_weights[2], w3 = g_weights[3];
    const float f = mask[n];
    const float* __restrict__ kr = Kn + (size_t)c * NP;
    const float* __restrict__ gr = G  + (size_t)c * NP;
    const int a0 = g_wi[0][n][0], a1 = g_wi[0][n][1];
    const int b0 = g_wi[1][n][0], b1 = g_wi[1][n][1];
    float acc = 0.f;
    if (f == 1.0f)
        acc = w0 * kr[a0] + w1 * kr[a1] + w2 * gr[b0] + w3 * gr[b1];
    if (n == 0) {
        const float kv = kr[0], gv = gr[0];
        acc += ((f == 1.f && a0 == 0) ? 0.f : w0) * kv
             + ((f == 1.f && a1 == 0) ? 0.f : w1) * kv
             + ((f == 1.f && b0 == 0) ? 0.f : w2) * gv
             + ((f == 1.f && b1 == 0) ? 0.f : w3) * gv;
    }
    out[(size_t)(2 * CC + c) * NP + n] = acc;
}

// ==================== launch ====================
extern "C" void kernel_launch(void* const* d_in, const int* in_sizes, int n_in,
                              void* d_out, int out_size) {
    const float* G    = (const float*)d_in[0];
    const float* Kn   = (const float*)d_in[1];
    const float* mask = (const float*)d_in[2];
    float* out = (float*)d_out;

    cudaFuncSetAttribute(gemm_tc, cudaFuncAttributeMaxDynamicSharedMemorySize, GEMM_SMEM);

    split_kernel<<<dim3(16, KSLICES, 2), 256>>>(G, Kn, out);  // + passthrough + norm partials
    compact_kernel<<<1, 1024>>>(mask);
    gemm_tc<<<dim3(16, 64, 2), 256, GEMM_SMEM>>>();   // y = rowtile*8 + kpart; extras exit
    top2_kernel<<<2048, 256>>>();                     // block per (z, compact row)
    weights_kernel<<<1, 1024>>>(mask);
    gather_kernel<<<4096, 1024>>>(G, Kn, mask, out);
}

// round 13
// speedup vs baseline: 5.7280x; 1.0809x over previous
#include <cuda_runtime.h>
#include <cuda_bf16.h>
#include <math.h>
#include <stdint.h>

#define NP 1024          // patches
#define CC 4096          // channels
#define NEGV (-1e30f)
#define KSLICES 16       // norm partial slices (256 k each)
#define KP 8             // split-K ways

// ---------------- device scratch ----------------
__device__ float g_par[KP][2u * 1024u * 1024u];   // raw dot partials [kp][z*2^20 + cr*NP + cm]
__device__ float g_normp[KSLICES][2][NP];         // norm partials at COMPACT positions
__device__ float g_cnr[2][NP];                    // rsqrt(norm) at compact positions [0]=G-masked,[1]=Kn-unmasked
__device__ float g_wv[2][NP][2];                  // zero-init; only masked rows written
__device__ int   g_wi[2][NP][2];
__device__ float g_weights[4];
__device__ int   g_nm;                            // masked count (rows / z=1 cols / G compact count)
__device__ int   g_ncol[2];
__device__ int   g_rowidx[NP];                    // compact row -> global
__device__ int   g_colidx[2][NP];                 // compact col -> global
__device__ int   g_dst[2][NP];                    // global patch -> compact slot (or -1) per mat
// COMPACT bf16 split operands: [mat][compact pos][k]. mat0 = G(flag==1), mat1 = Kn(flag==0)
__device__ __nv_bfloat16 g_chi[2][NP][CC];
__device__ __nv_bfloat16 g_clo[2][NP][CC];

// ==================== compaction (mask only; runs FIRST) ====================
__global__ void compact_kernel(const float* __restrict__ mask) {
    __shared__ int wsum1[32], wsum0[32];
    const int n = threadIdx.x;                 // 1024 threads
    const int lane = n & 31, w = n >> 5;
    const int f = (mask[n] == 1.0f) ? 1 : 0;
    const unsigned bal1 = __ballot_sync(0xffffffffu, f);
    const unsigned bal0 = ~bal1;
    const int pre1 = __popc(bal1 & ((1u << lane) - 1u));
    const int pre0 = __popc(bal0 & ((1u << lane) - 1u));
    if (lane == 0) { wsum1[w] = __popc(bal1); wsum0[w] = __popc(bal0); }
    __syncthreads();
    if (w == 0) {
        int v1 = wsum1[lane], o1 = v1;
        int v0 = wsum0[lane], o0 = v0;
        #pragma unroll
        for (int off = 1; off < 32; off <<= 1) {
            int t1 = __shfl_up_sync(0xffffffffu, v1, off);
            int t0 = __shfl_up_sync(0xffffffffu, v0, off);
            if (lane >= off) { v1 += t1; v0 += t0; }
        }
        wsum1[lane] = v1 - o1;
        wsum0[lane] = v0 - o0;
        if (lane == 31) { g_nm = v1; g_ncol[1] = v1; g_ncol[0] = v0; }
    }
    __syncthreads();
    if (f) {
        const int p = wsum1[w] + pre1;
        g_rowidx[p] = n;
        g_colidx[1][p] = n;
        g_dst[0][n] = p;      // G patch needed at compact slot p
        g_dst[1][n] = -1;     // Kn patch not needed
    } else {
        const int p = wsum0[w] + pre0;
        g_colidx[0][p] = n;
        g_dst[0][n] = -1;
        g_dst[1][n] = p;
    }
    __syncthreads();
    const int nm = g_nm;
    if (n >= nm)      { g_rowidx[n] = 0; g_colidx[1][n] = 0; }
    if (n >= NP - nm) { g_colidx[0][n] = 0; }
}

// ==================== fused split(compact) + passthrough + norm partials ====================
__global__ __launch_bounds__(256) void split_kernel(const float* __restrict__ G,
                                                    const float* __restrict__ Kn,
                                                    float* __restrict__ out) {
    const int mat = blockIdx.z;
    const float* __restrict__ X = mat ? Kn : G;
    float* __restrict__ outp = out + (size_t)mat * CC * NP;
    __shared__ float tile[64][65];
    __shared__ float snorm[4][64];
    __shared__ int s_dst[64];

    const int n0 = blockIdx.x * 64;
    const int kq0 = blockIdx.y * 256;
    const int tid = threadIdx.x;
    const int nn = tid & 63;
    const int kseg = tid >> 6;
    if (tid < 64) s_dst[tid] = g_dst[mat][n0 + tid];
    float norm = 0.f;

    for (int it = 0; it < 4; ++it) {
        const int k0 = kq0 + it * 64;
        #pragma unroll
        for (int p = 0; p < 4; ++p) {
            const int r = p * 16 + (tid >> 4);
            const int c = (tid & 15) * 4;
            const size_t gi = (size_t)(k0 + r) * NP + n0 + c;
            const float4 v = *(const float4*)(X + gi);
            *(float4*)(outp + gi) = v;
            tile[r][c]     = v.x;
            tile[r][c + 1] = v.y;
            tile[r][c + 2] = v.z;
            tile[r][c + 3] = v.w;
        }
        __syncthreads();
        const int dst = s_dst[nn];
        if (dst >= 0) {
            float vv[16];
            #pragma unroll
            for (int j = 0; j < 16; ++j) {
                const float v = tile[kseg * 16 + j][nn];
                vv[j] = v;
                norm += v * v;
            }
            __nv_bfloat16 hb[16], lb[16];
            #pragma unroll
            for (int j = 0; j < 16; ++j) {
                const __nv_bfloat16 h = __float2bfloat16(vv[j]);
                hb[j] = h;
                lb[j] = __float2bfloat16(vv[j] - __bfloat162float(h));
            }
            __nv_bfloat16* __restrict__ hd = &g_chi[mat][dst][k0 + kseg * 16];
            __nv_bfloat16* __restrict__ ld = &g_clo[mat][dst][k0 + kseg * 16];
            *(uint4*)(hd)     = *(const uint4*)&hb[0];
            *(uint4*)(hd + 8) = *(const uint4*)&hb[8];
            *(uint4*)(ld)     = *(const uint4*)&lb[0];
            *(uint4*)(ld + 8) = *(const uint4*)&lb[8];
        }
        __syncthreads();
    }
    snorm[kseg][nn] = norm;
    __syncthreads();
    if (kseg == 0 && s_dst[nn] >= 0)
        g_normp[blockIdx.y][mat][s_dst[nn]] =
            snorm[0][nn] + snorm[1][nn] + snorm[2][nn] + snorm[3][nn];
}

// ==================== norm combine -> rsqrt tables ====================
__global__ void normr_kernel() {
    const int mat = blockIdx.x;
    const int n = threadIdx.x;       // 1024
    float s = 0.f;
    #pragma unroll
    for (int q = 0; q < KSLICES; ++q) s += g_normp[q][mat][n];
    g_cnr[mat][n] = rsqrtf(s);
}

// ==================== helpers ====================
__device__ __forceinline__ uint32_t s2u(const void* p) {
    uint32_t a;
    asm("{ .reg .u64 t; cvta.to.shared.u64 t, %1; cvt.u32.u64 %0, t; }" : "=r"(a) : "l"(p));
    return a;
}
#define CP16(dst, src) \
    asm volatile("cp.async.cg.shared.global [%0], [%1], 16;\n" :: "r"(dst), "l"(src))
#define CP_COMMIT() asm volatile("cp.async.commit_group;\n" ::: "memory")

__device__ __forceinline__ uint32_t smaddr(uint32_t base, int row, int chunk) {
    return base + row * 64 + ((chunk ^ ((row >> 1) & 3)) << 4);
}

// ==================== HMMA GEMM: compact direct, split-K 8 ====================
#define STAGES 4
#define BKC 32
#define NCHUNK 48                // 3 phases * 16 chunks of K=32 (512 k per kpart)
#define A_BYTES 8192
#define B_BYTES 4096
#define STAGE_BYTES (A_BYTES + B_BYTES)
#define GEMM_SMEM (STAGES * STAGE_BYTES)   // 48 KB dynamic

__global__ __launch_bounds__(256) void gemm_tc() {
    const int z = blockIdx.z;
    const int rt = blockIdx.y >> 3;
    const int kp = blockIdx.y & 7;
    const int n0 = rt * 128;
    const int m0 = blockIdx.x * 64;
    if (n0 >= g_nm || m0 >= g_ncol[z]) return;

    extern __shared__ __align__(1024) char dsm[];
    const int tid = threadIdx.x, wid = tid >> 5, lid = tid & 31;
    const uint32_t sbase = s2u(dsm);

    const int wm = wid >> 1;       // 0..3 -> m offset wm*32
    const int wn = wid & 1;        // 0..1 -> n offset wn*32

    const __nv_bfloat16* __restrict__ Ahi = &g_chi[0][0][0];
    const __nv_bfloat16* __restrict__ Alo = &g_clo[0][0][0];
    const __nv_bfloat16* __restrict__ Bhi = z ? &g_chi[0][0][0] : &g_chi[1][0][0];
    const __nv_bfloat16* __restrict__ Blo = z ? &g_clo[0][0][0] : &g_clo[1][0][0];
    const int kbase = kp * 512;

    auto load_stage = [&](int st, int c) {
        const int ph = c >> 4;                 // 0:hh 1:lh 2:hl
        const int kk = kbase + (c & 15) * BKC;
        const __nv_bfloat16* __restrict__ Ap = (ph == 1) ? Alo : Ahi;
        const __nv_bfloat16* __restrict__ Bp = (ph == 2) ? Blo : Bhi;
        const uint32_t sA = sbase + st * STAGE_BYTES;
        const uint32_t sB = sA + A_BYTES;
        #pragma unroll
        for (int i = 0; i < 2; i++) {
            const int e = tid + (i << 8);
            const int r = e >> 2, cb = e & 3;
            CP16(smaddr(sA, r, cb), Ap + (size_t)(n0 + r) * CC + kk + cb * 8);
        }
        {
            const int r = tid >> 2, cb = tid & 3;
            CP16(smaddr(sB, r, cb), Bp + (size_t)(m0 + r) * CC + kk + cb * 8);
        }
    };

    #pragma unroll
    for (int p = 0; p < STAGES - 1; p++) { load_stage(p, p); CP_COMMIT(); }

    float acc[2][4][4];
    #pragma unroll
    for (int a = 0; a < 2; a++)
        #pragma unroll
        for (int b = 0; b < 4; b++)
            #pragma unroll
            for (int d = 0; d < 4; d++) acc[a][b][d] = 0.f;

    for (int c = 0; c < NCHUNK; c++) {
        const int st = c & (STAGES - 1);
        if (c <= NCHUNK - 3)      asm volatile("cp.async.wait_group 2;\n" ::: "memory");
        else if (c == NCHUNK - 2) asm volatile("cp.async.wait_group 1;\n" ::: "memory");
        else                      asm volatile("cp.async.wait_group 0;\n" ::: "memory");
        __syncthreads();

        const int nc = c + STAGES - 1;
        if (nc < NCHUNK) { load_stage(nc & (STAGES - 1), nc); CP_COMMIT(); }

        const uint32_t sA = sbase + st * STAGE_BYTES;
        const uint32_t sB = sA + A_BYTES;
        #pragma unroll
        for (int ks = 0; ks < 2; ks++) {
            uint32_t af[2][4], bf[4][2];
            #pragma unroll
            for (int mi = 0; mi < 2; mi++) {
                const int row = wm * 32 + mi * 16 + (lid & 15);
                const int ch = ks * 2 + (lid >> 4);
                asm volatile("ldmatrix.sync.aligned.m8n8.x4.shared.b16 {%0,%1,%2,%3}, [%4];"
                             : "=r"(af[mi][0]), "=r"(af[mi][1]), "=r"(af[mi][2]), "=r"(af[mi][3])
                             : "r"(smaddr(sA, row, ch)));
            }
            #pragma unroll
            for (int nip = 0; nip < 2; nip++) {
                const int row = wn * 32 + nip * 16 + ((lid >> 4) & 1) * 8 + (lid & 7);
                const int ch = ks * 2 + ((lid >> 3) & 1);
                asm volatile("ldmatrix.sync.aligned.m8n8.x4.shared.b16 {%0,%1,%2,%3}, [%4];"
                             : "=r"(bf[2 * nip][0]), "=r"(bf[2 * nip][1]),
                               "=r"(bf[2 * nip + 1][0]), "=r"(bf[2 * nip + 1][1])
                             : "r"(smaddr(sB, row, ch)));
            }
            #pragma unroll
            for (int mi = 0; mi < 2; mi++)
                #pragma unroll
                for (int ni = 0; ni < 4; ni++)
                    asm volatile(
                        "mma.sync.aligned.m16n8k16.row.col.f32.bf16.bf16.f32 "
                        "{%0,%1,%2,%3}, {%4,%5,%6,%7}, {%8,%9}, {%0,%1,%2,%3};"
                        : "+f"(acc[mi][ni][0]), "+f"(acc[mi][ni][1]),
                          "+f"(acc[mi][ni][2]), "+f"(acc[mi][ni][3])
                        : "r"(af[mi][0]), "r"(af[mi][1]), "r"(af[mi][2]), "r"(af[mi][3]),
                          "r"(bf[ni][0]), "r"(bf[ni][1]));
        }
    }

    const int g = lid >> 2, tc = lid & 3;
    float* __restrict__ zbase = &g_par[kp][0] + ((size_t)z << 20);
    #pragma unroll
    for (int mi = 0; mi < 2; mi++) {
        const int r0 = wm * 32 + mi * 16 + g;
        const int r1 = r0 + 8;
        float* __restrict__ p0 = zbase + (size_t)(n0 + r0) * NP + m0;
        float* __restrict__ p1 = zbase + (size_t)(n0 + r1) * NP + m0;
        #pragma unroll
        for (int ni = 0; ni < 4; ni++) {
            const int col = wn * 32 + ni * 8 + 2 * tc;
            float2 o0, o1;
            o0.x = acc[mi][ni][0]; o0.y = acc[mi][ni][1];
            o1.x = acc[mi][ni][2]; o1.y = acc[mi][ni][3];
            *(float2*)(p0 + col) = o0;
            *(float2*)(p1 + col) = o1;
        }
    }
}

// ==================== block-per-row 8-way reduce + normalize + top-2 ====================
__device__ __forceinline__ void ins2(float v, int idx, float& v1, int& i1, float& v2, int& i2) {
    if (v > v1 || (v == v1 && idx < i1)) { v2 = v1; i2 = i1; v1 = v; i1 = idx; }
    else if (v > v2 || (v == v2 && idx < i2)) { v2 = v; i2 = idx; }
}

__global__ __launch_bounds__(256) void top2_kernel() {
    const int bid = blockIdx.x;
    const int z = bid >> 10, cr = bid & 1023;
    if (cr >= g_nm) return;
    const int cnt = g_ncol[z];
    const int tid = threadIdx.x, lane = tid & 31, wid = tid >> 5;
    const int orig = g_rowidx[cr];
    const float rn = g_cnr[0][cr];
    const float* __restrict__ cnr = z ? g_cnr[0] : g_cnr[1];
    const size_t off = ((size_t)z << 20) + (size_t)cr * NP;

    float v1 = -3.4e38f, v2 = -3.4e38f;
    int i1 = 0x7fffffff, i2 = 0x7fffffff;
    const int m = tid * 4;
    if (m < cnt) {
        float4 s = *(const float4*)(&g_par[0][0] + off + m);
        #pragma unroll
        for (int q = 1; q < KP; q++) {
            const float4 a = *(const float4*)(&g_par[q][0] + off + m);
            s.x += a.x; s.y += a.y; s.z += a.z; s.w += a.w;
        }
        const float4 rc = *(const float4*)(cnr + m);
        float sv[4] = {s.x * rc.x, s.y * rc.y, s.z * rc.z, s.w * rc.w};
        #pragma unroll
        for (int j = 0; j < 4; j++) {
            const float v = (m + j < cnt) ? sv[j] * rn : NEGV;
            if (v > v1) { v2 = v1; i2 = i1; v1 = v; i1 = m + j; }
            else if (v > v2) { v2 = v; i2 = m + j; }
        }
    }
    for (int o = 16; o; o >>= 1) {
        float ov1 = __shfl_down_sync(0xffffffffu, v1, o);
        int   oi1 = __shfl_down_sync(0xffffffffu, i1, o);
        float ov2 = __shfl_down_sync(0xffffffffu, v2, o);
        int   oi2 = __shfl_down_sync(0xffffffffu, i2, o);
        ins2(ov1, oi1, v1, i1, v2, i2);
        ins2(ov2, oi2, v1, i1, v2, i2);
    }
    __shared__ float sv1[8], sv2[8];
    __shared__ int   si1[8], si2[8];
    if (lane == 0) { sv1[wid] = v1; si1[wid] = i1; sv2[wid] = v2; si2[wid] = i2; }
    __syncthreads();
    if (wid == 0) {
        if (lane < 8) { v1 = sv1[lane]; i1 = si1[lane]; v2 = sv2[lane]; i2 = si2[lane]; }
        else { v1 = v2 = -3.4e38f; i1 = i2 = 0x7fffffff; }
        for (int o = 4; o; o >>= 1) {
            float ov1 = __shfl_down_sync(0xffffffffu, v1, o);
            int   oi1 = __shfl_down_sync(0xffffffffu, i1, o);
            float ov2 = __shfl_down_sync(0xffffffffu, v2, o);
            int   oi2 = __shfl_down_sync(0xffffffffu, i2, o);
            ins2(ov1, oi1, v1, i1, v2, i2);
            ins2(ov2, oi2, v1, i1, v2, i2);
        }
        if (lane == 0) {
            g_wv[z][orig][0] = v1;
            g_wv[z][orig][1] = v2;
            g_wi[z][orig][0] = g_colidx[z][i1];
            g_wi[z][orig][1] = g_colidx[z][i2];
        }
    }
}

// ==================== means + softmax (parallel final reduce) ====================
__global__ void weights_kernel(const float* __restrict__ mask) {
    const int n = threadIdx.x;
    const float f = mask[n];
    float s[5];
    s[0] = f;
    s[1] = g_wv[0][n][0] * f;
    s[2] = g_wv[0][n][1] * f;
    s[3] = g_wv[1][n][0] * f;
    s[4] = g_wv[1][n][1] * f;
    __shared__ float sm[5][32];
    __shared__ float tots[5];
    const int lane = n & 31, w = n >> 5;
    #pragma unroll
    for (int k = 0; k < 5; k++) {
        float v = s[k];
        for (int off = 16; off; off >>= 1) v += __shfl_down_sync(0xffffffffu, v, off);
        if (lane == 0) sm[k][w] = v;
    }
    __syncthreads();
    if (w < 5) {
        float v = sm[w][lane];
        for (int off = 16; off; off >>= 1) v += __shfl_down_sync(0xffffffffu, v, off);
        if (lane == 0) tots[w] = v;
    }
    __syncthreads();
    if (n == 0) {
        const float nm = tots[0];
        float mean[4];
        #pragma unroll
        for (int j = 0; j < 4; j++) mean[j] = tots[j + 1] / nm;
        float mx = mean[0];
        #pragma unroll
        for (int j = 1; j < 4; j++) mx = fmaxf(mx, mean[j]);
        float e[4], se = 0.f;
        #pragma unroll
        for (int j = 0; j < 4; j++) { e[j] = expf(mean[j] - mx); se += e[j]; }
        #pragma unroll
        for (int j = 0; j < 4; j++) g_weights[j] = e[j] / se;
    }
}

// ==================== gather: 8 channels per block ====================
__global__ __launch_bounds__(1024) void gather_kernel(const float* __restrict__ G,
                                                      const float* __restrict__ Kn,
                                                      const float* __restrict__ mask,
                                                      float* __restrict__ out) {
    const int c0 = blockIdx.x * 8;
    const int n = threadIdx.x;
    const float w0 = g_weights[0], w1 = g_weights[1], w2 = g_weights[2], w3 = g_weights[3];
    const float f = mask[n];
    const int a0 = g_wi[0][n][0], a1 = g_wi[0][n][1];
    const int b0 = g_wi[1][n][0], b1 = g_wi[1][n][1];
    const bool msk = (f == 1.0f);
    #pragma unroll
    for (int ch = 0; ch < 8; ch++) {
        const int c = c0 + ch;
        const float* __restrict__ kr = Kn + (size_t)c * NP;
        const float* __restrict__ gr = G  + (size_t)c * NP;
        float acc = 0.f;
        if (msk)
            acc = w0 * kr[a0] + w1 * kr[a1] + w2 * gr[b0] + w3 * gr[b1];
        if (n == 0) {
            const float kv = kr[0], gv = gr[0];
            acc += ((msk && a0 == 0) ? 0.f : w0) * kv
                 + ((msk && a1 == 0) ? 0.f : w1) * kv
                 + ((msk && b0 == 0) ? 0.f : w2) * gv
                 + ((msk && b1 == 0) ? 0.f : w3) * gv;
        }
        out[(size_t)(2 * CC + c) * NP + n] = acc;
    }
}

// ==================== launch ====================
extern "C" void kernel_launch(void* const* d_in, const int* in_sizes, int n_in,
                              void* d_out, int out_size) {
    const float* G    = (const float*)d_in[0];
    const float* Kn   = (const float*)d_in[1];
    const float* mask = (const float*)d_in[2];
    float* out = (float*)d_out;

    cudaFuncSetAttribute(gemm_tc, cudaFuncAttributeMaxDynamicSharedMemorySize, GEMM_SMEM);

    compact_kernel<<<1, 1024>>>(mask);
    split_kernel<<<dim3(16, KSLICES, 2), 256>>>(G, Kn, out);  // compacted convert + passthrough
    normr_kernel<<<2, 1024>>>();
    gemm_tc<<<dim3(16, 64, 2), 256, GEMM_SMEM>>>();
    top2_kernel<<<2048, 256>>>();
    weights_kernel<<<1, 1024>>>(mask);
    gather_kernel<<<512, 1024>>>(G, Kn, mask, out);
}

// round 14
// speedup vs baseline: 6.2627x; 1.0933x over previous
#include <cuda_runtime.h>
#include <cuda_bf16.h>
#include <math.h>
#include <stdint.h>

#define NP 1024          // patches
#define CC 4096          // channels
#define NEGV (-1e30f)
#define KSLICES 16       // norm partial slices (256 k each)
#define KP 8             // split-K ways

// ---------------- device scratch ----------------
__device__ float g_par[KP][2u * 1024u * 1024u];   // raw dot partials [kp][z*2^20 + cr*NP + cm]
__device__ float g_normp[KSLICES][2][NP];         // norm partials at COMPACT positions
__device__ float g_cnr[2][NP];                    // rsqrt(norm) at compact positions
__device__ float g_wv[2][NP][2];
__device__ int   g_wi[2][NP][2];
__device__ float g_weights[4];
__device__ int   g_nm;
__device__ int   g_ncol[2];
__device__ int   g_rowidx[NP];
__device__ int   g_colidx[2][NP];
__device__ int   g_dst[2][NP];                    // global patch -> compact slot (or -1) per mat
// COMPACT bf16 split operands: [mat][compact pos][k]. mat0 = G(flag==1), mat1 = Kn(flag==0)
__device__ __nv_bfloat16 g_chi[2][NP][CC];
__device__ __nv_bfloat16 g_clo[2][NP][CC];

// ==================== compaction ====================
__global__ void compact_kernel(const float* __restrict__ mask) {
    __shared__ int wsum1[32], wsum0[32];
    const int n = threadIdx.x;
    const int lane = n & 31, w = n >> 5;
    const int f = (mask[n] == 1.0f) ? 1 : 0;
    const unsigned bal1 = __ballot_sync(0xffffffffu, f);
    const unsigned bal0 = ~bal1;
    const int pre1 = __popc(bal1 & ((1u << lane) - 1u));
    const int pre0 = __popc(bal0 & ((1u << lane) - 1u));
    if (lane == 0) { wsum1[w] = __popc(bal1); wsum0[w] = __popc(bal0); }
    __syncthreads();
    if (w == 0) {
        int v1 = wsum1[lane], o1 = v1;
        int v0 = wsum0[lane], o0 = v0;
        #pragma unroll
        for (int off = 1; off < 32; off <<= 1) {
            int t1 = __shfl_up_sync(0xffffffffu, v1, off);
            int t0 = __shfl_up_sync(0xffffffffu, v0, off);
            if (lane >= off) { v1 += t1; v0 += t0; }
        }
        wsum1[lane] = v1 - o1;
        wsum0[lane] = v0 - o0;
        if (lane == 31) { g_nm = v1; g_ncol[1] = v1; g_ncol[0] = v0; }
    }
    __syncthreads();
    if (f) {
        const int p = wsum1[w] + pre1;
        g_rowidx[p] = n;
        g_colidx[1][p] = n;
        g_dst[0][n] = p;
        g_dst[1][n] = -1;
    } else {
        const int p = wsum0[w] + pre0;
        g_colidx[0][p] = n;
        g_dst[0][n] = -1;
        g_dst[1][n] = p;
    }
    __syncthreads();
    const int nm = g_nm;
    if (n >= nm)      { g_rowidx[n] = 0; g_colidx[1][n] = 0; }
    if (n >= NP - nm) { g_colidx[0][n] = 0; }
}

// ==================== split(compact) + norm partials (no passthrough) ====================
__global__ __launch_bounds__(256) void split_kernel(const float* __restrict__ G,
                                                    const float* __restrict__ Kn) {
    const int mat = blockIdx.z;
    const float* __restrict__ X = mat ? Kn : G;
    __shared__ float tile[64][65];
    __shared__ float snorm[4][64];
    __shared__ int s_dst[64];

    const int n0 = blockIdx.x * 64;
    const int kq0 = blockIdx.y * 256;
    const int tid = threadIdx.x;
    const int nn = tid & 63;
    const int kseg = tid >> 6;
    if (tid < 64) s_dst[tid] = g_dst[mat][n0 + tid];
    float norm = 0.f;

    for (int it = 0; it < 4; ++it) {
        const int k0 = kq0 + it * 64;
        #pragma unroll
        for (int p = 0; p < 4; ++p) {
            const int r = p * 16 + (tid >> 4);
            const int c = (tid & 15) * 4;
            const size_t gi = (size_t)(k0 + r) * NP + n0 + c;
            const float4 v = *(const float4*)(X + gi);
            tile[r][c]     = v.x;
            tile[r][c + 1] = v.y;
            tile[r][c + 2] = v.z;
            tile[r][c + 3] = v.w;
        }
        __syncthreads();
        const int dst = s_dst[nn];
        if (dst >= 0) {
            float vv[16];
            #pragma unroll
            for (int j = 0; j < 16; ++j) {
                const float v = tile[kseg * 16 + j][nn];
                vv[j] = v;
                norm += v * v;
            }
            __nv_bfloat16 hb[16], lb[16];
            #pragma unroll
            for (int j = 0; j < 16; ++j) {
                const __nv_bfloat16 h = __float2bfloat16(vv[j]);
                hb[j] = h;
                lb[j] = __float2bfloat16(vv[j] - __bfloat162float(h));
            }
            __nv_bfloat16* __restrict__ hd = &g_chi[mat][dst][k0 + kseg * 16];
            __nv_bfloat16* __restrict__ ld = &g_clo[mat][dst][k0 + kseg * 16];
            *(uint4*)(hd)     = *(const uint4*)&hb[0];
            *(uint4*)(hd + 8) = *(const uint4*)&hb[8];
            *(uint4*)(ld)     = *(const uint4*)&lb[0];
            *(uint4*)(ld + 8) = *(const uint4*)&lb[8];
        }
        __syncthreads();
    }
    snorm[kseg][nn] = norm;
    __syncthreads();
    if (kseg == 0 && s_dst[nn] >= 0)
        g_normp[blockIdx.y][mat][s_dst[nn]] =
            snorm[0][nn] + snorm[1][nn] + snorm[2][nn] + snorm[3][nn];
}

// ==================== norm combine -> rsqrt tables ====================
__global__ void normr_kernel() {
    const int mat = blockIdx.x;
    const int n = threadIdx.x;
    float s = 0.f;
    #pragma unroll
    for (int q = 0; q < KSLICES; ++q) s += g_normp[q][mat][n];
    g_cnr[mat][n] = rsqrtf(s);
}

// ==================== helpers ====================
__device__ __forceinline__ uint32_t s2u(const void* p) {
    uint32_t a;
    asm("{ .reg .u64 t; cvta.to.shared.u64 t, %1; cvt.u32.u64 %0, t; }" : "=r"(a) : "l"(p));
    return a;
}
#define CP16(dst, src) \
    asm volatile("cp.async.cg.shared.global [%0], [%1], 16;\n" :: "r"(dst), "l"(src))
#define CP_COMMIT() asm volatile("cp.async.commit_group;\n" ::: "memory")

__device__ __forceinline__ uint32_t smaddr(uint32_t base, int row, int chunk) {
    return base + row * 64 + ((chunk ^ ((row >> 1) & 3)) << 4);
}

// ==================== HMMA GEMM + z=1 symmetry + embedded passthrough copy ====================
#define STAGES 4
#define BKC 32
#define NCHUNK 48
#define A_BYTES 8192
#define B_BYTES 4096
#define STAGE_BYTES (A_BYTES + B_BYTES)
#define GEMM_SMEM (STAGES * STAGE_BYTES)   // 48 KB dynamic

__global__ __launch_bounds__(256) void gemm_tc(const float* __restrict__ G,
                                               const float* __restrict__ Kn,
                                               float* __restrict__ out) {
    const int rawy = blockIdx.y;
    const int tid = threadIdx.x;
    const int z = blockIdx.z;

    // ---- copy CTAs: rawy in [64,72) -> passthrough G,Kn -> out ----
    if (rawy >= 64) {
        const int ci = ((rawy - 64) * 16 + blockIdx.x) + z * 128;   // 0..255
        const float4* __restrict__ s = (ci < 128)
            ? ((const float4*)G)  + (size_t)ci * 8192
            : ((const float4*)Kn) + (size_t)(ci - 128) * 8192;
        float4* __restrict__ d = ((float4*)out) + (size_t)ci * 8192;
        #pragma unroll 8
        for (int i = 0; i < 32; i++)
            d[i * 256 + tid] = s[i * 256 + tid];
        return;
    }

    const int rt = rawy >> 3;
    const int kp = rawy & 7;
    const int n0 = rt * 128;
    const int m0 = blockIdx.x * 64;
    if (n0 >= g_nm || m0 >= g_ncol[z]) return;
    if (z == 1 && m0 >= n0 + 128) return;        // symmetric: skip strictly-upper tiles

    extern __shared__ __align__(1024) char dsm[];
    const int wid = tid >> 5, lid = tid & 31;
    const uint32_t sbase = s2u(dsm);

    const int wm = wid >> 1;
    const int wn = wid & 1;

    const __nv_bfloat16* __restrict__ Ahi = &g_chi[0][0][0];
    const __nv_bfloat16* __restrict__ Alo = &g_clo[0][0][0];
    const __nv_bfloat16* __restrict__ Bhi = z ? &g_chi[0][0][0] : &g_chi[1][0][0];
    const __nv_bfloat16* __restrict__ Blo = z ? &g_clo[0][0][0] : &g_clo[1][0][0];
    const int kbase = kp * 512;

    auto load_stage = [&](int st, int c) {
        const int ph = c >> 4;
        const int kk = kbase + (c & 15) * BKC;
        const __nv_bfloat16* __restrict__ Ap = (ph == 1) ? Alo : Ahi;
        const __nv_bfloat16* __restrict__ Bp = (ph == 2) ? Blo : Bhi;
        const uint32_t sA = sbase + st * STAGE_BYTES;
        const uint32_t sB = sA + A_BYTES;
        #pragma unroll
        for (int i = 0; i < 2; i++) {
            const int e = tid + (i << 8);
            const int r = e >> 2, cb = e & 3;
            CP16(smaddr(sA, r, cb), Ap + (size_t)(n0 + r) * CC + kk + cb * 8);
        }
        {
            const int r = tid >> 2, cb = tid & 3;
            CP16(smaddr(sB, r, cb), Bp + (size_t)(m0 + r) * CC + kk + cb * 8);
        }
    };

    #pragma unroll
    for (int p = 0; p < STAGES - 1; p++) { load_stage(p, p); CP_COMMIT(); }

    float acc[2][4][4];
    #pragma unroll
    for (int a = 0; a < 2; a++)
        #pragma unroll
        for (int b = 0; b < 4; b++)
            #pragma unroll
            for (int d = 0; d < 4; d++) acc[a][b][d] = 0.f;

    for (int c = 0; c < NCHUNK; c++) {
        const int st = c & (STAGES - 1);
        if (c <= NCHUNK - 3)      asm volatile("cp.async.wait_group 2;\n" ::: "memory");
        else if (c == NCHUNK - 2) asm volatile("cp.async.wait_group 1;\n" ::: "memory");
        else                      asm volatile("cp.async.wait_group 0;\n" ::: "memory");
        __syncthreads();

        const int nc = c + STAGES - 1;
        if (nc < NCHUNK) { load_stage(nc & (STAGES - 1), nc); CP_COMMIT(); }

        const uint32_t sA = sbase + st * STAGE_BYTES;
        const uint32_t sB = sA + A_BYTES;
        #pragma unroll
        for (int ks = 0; ks < 2; ks++) {
            uint32_t af[2][4], bf[4][2];
            #pragma unroll
            for (int mi = 0; mi < 2; mi++) {
                const int row = wm * 32 + mi * 16 + (lid & 15);
                const int ch = ks * 2 + (lid >> 4);
                asm volatile("ldmatrix.sync.aligned.m8n8.x4.shared.b16 {%0,%1,%2,%3}, [%4];"
                             : "=r"(af[mi][0]), "=r"(af[mi][1]), "=r"(af[mi][2]), "=r"(af[mi][3])
                             : "r"(smaddr(sA, row, ch)));
            }
            #pragma unroll
            for (int nip = 0; nip < 2; nip++) {
                const int row = wn * 32 + nip * 16 + ((lid >> 4) & 1) * 8 + (lid & 7);
                const int ch = ks * 2 + ((lid >> 3) & 1);
                asm volatile("ldmatrix.sync.aligned.m8n8.x4.shared.b16 {%0,%1,%2,%3}, [%4];"
                             : "=r"(bf[2 * nip][0]), "=r"(bf[2 * nip][1]),
                               "=r"(bf[2 * nip + 1][0]), "=r"(bf[2 * nip + 1][1])
                             : "r"(smaddr(sB, row, ch)));
            }
            #pragma unroll
            for (int mi = 0; mi < 2; mi++)
                #pragma unroll
                for (int ni = 0; ni < 4; ni++)
                    asm volatile(
                        "mma.sync.aligned.m16n8k16.row.col.f32.bf16.bf16.f32 "
                        "{%0,%1,%2,%3}, {%4,%5,%6,%7}, {%8,%9}, {%0,%1,%2,%3};"
                        : "+f"(acc[mi][ni][0]), "+f"(acc[mi][ni][1]),
                          "+f"(acc[mi][ni][2]), "+f"(acc[mi][ni][3])
                        : "r"(af[mi][0]), "r"(af[mi][1]), "r"(af[mi][2]), "r"(af[mi][3]),
                          "r"(bf[ni][0]), "r"(bf[ni][1]));
        }
    }

    const int g = lid >> 2, tc = lid & 3;
    float* __restrict__ zbase = &g_par[kp][0] + ((size_t)z << 20);

    if (z == 0) {
        // full rectangle, plain stores
        #pragma unroll
        for (int mi = 0; mi < 2; mi++) {
            const int r0 = wm * 32 + mi * 16 + g;
            const int r1 = r0 + 8;
            float* __restrict__ p0 = zbase + (size_t)(n0 + r0) * NP + m0;
            float* __restrict__ p1 = zbase + (size_t)(n0 + r1) * NP + m0;
            #pragma unroll
            for (int ni = 0; ni < 4; ni++) {
                const int col = wn * 32 + ni * 8 + 2 * tc;
                float2 o0, o1;
                o0.x = acc[mi][ni][0]; o0.y = acc[mi][ni][1];
                o1.x = acc[mi][ni][2]; o1.y = acc[mi][ni][3];
                *(float2*)(p0 + col) = o0;
                *(float2*)(p1 + col) = o1;
            }
        }
    } else {
        // z=1 symmetric: normal store only C <= R; transposed store (via smem) only R > C
        #pragma unroll
        for (int mi = 0; mi < 2; mi++) {
            const int r0 = wm * 32 + mi * 16 + g;
            const int r1 = r0 + 8;
            const int R0 = n0 + r0, R1 = n0 + r1;
            float* __restrict__ p0 = zbase + (size_t)R0 * NP + m0;
            float* __restrict__ p1 = zbase + (size_t)R1 * NP + m0;
            #pragma unroll
            for (int ni = 0; ni < 4; ni++) {
                const int col = wn * 32 + ni * 8 + 2 * tc;
                const int C0 = m0 + col, C1 = C0 + 1;
                if (C0 <= R0) p0[col]     = acc[mi][ni][0];
                if (C1 <= R0) p0[col + 1] = acc[mi][ni][1];
                if (C0 <= R1) p1[col]     = acc[mi][ni][2];
                if (C1 <= R1) p1[col + 1] = acc[mi][ni][3];
            }
        }
        // stage transposed tile into smem: smemT[cl][rl], pitch 129
        __syncthreads();          // all stage smem consumption done (wait_group 0 passed)
        float* __restrict__ smemT = (float*)dsm;
        #pragma unroll
        for (int mi = 0; mi < 2; mi++) {
            const int r0 = wm * 32 + mi * 16 + g;
            const int r1 = r0 + 8;
            #pragma unroll
            for (int ni = 0; ni < 4; ni++) {
                const int col = wn * 32 + ni * 8 + 2 * tc;
                smemT[(col)     * 129 + r0] = acc[mi][ni][0];
                smemT[(col + 1) * 129 + r0] = acc[mi][ni][1];
                smemT[(col)     * 129 + r1] = acc[mi][ni][2];
                smemT[(col + 1) * 129 + r1] = acc[mi][ni][3];
            }
        }
        __syncthreads();
        // write transposed: target row = m0+cl, target cols = n0+rl; only where n0+rl > m0+cl
        for (int e = tid; e < 64 * 128; e += 256) {
            const int rl = e & 127, cl = e >> 7;
            if (n0 + rl > m0 + cl)
                zbase[(size_t)(m0 + cl) * NP + n0 + rl] = smemT[cl * 129 + rl];
        }
    }
}

// ==================== block-per-row 8-way reduce + normalize + top-2 ====================
__device__ __forceinline__ void ins2(float v, int idx, float& v1, int& i1, float& v2, int& i2) {
    if (v > v1 || (v == v1 && idx < i1)) { v2 = v1; i2 = i1; v1 = v; i1 = idx; }
    else if (v > v2 || (v == v2 && idx < i2)) { v2 = v; i2 = idx; }
}

__global__ __launch_bounds__(256) void top2_kernel() {
    const int bid = blockIdx.x;
    const int z = bid >> 10, cr = bid & 1023;
    if (cr >= g_nm) return;
    const int cnt = g_ncol[z];
    const int tid = threadIdx.x, lane = tid & 31, wid = tid >> 5;
    const int orig = g_rowidx[cr];
    const float rn = g_cnr[0][cr];
    const float* __restrict__ cnr = z ? g_cnr[0] : g_cnr[1];
    const size_t off = ((size_t)z << 20) + (size_t)cr * NP;

    float v1 = -3.4e38f, v2 = -3.4e38f;
    int i1 = 0x7fffffff, i2 = 0x7fffffff;
    const int m = tid * 4;
    if (m < cnt) {
        float4 s = *(const float4*)(&g_par[0][0] + off + m);
        #pragma unroll
        for (int q = 1; q < KP; q++) {
            const float4 a = *(const float4*)(&g_par[q][0] + off + m);
            s.x += a.x; s.y += a.y; s.z += a.z; s.w += a.w;
        }
        const float4 rc = *(const float4*)(cnr + m);
        float sv[4] = {s.x * rc.x, s.y * rc.y, s.z * rc.z, s.w * rc.w};
        #pragma unroll
        for (int j = 0; j < 4; j++) {
            const float v = (m + j < cnt) ? sv[j] * rn : NEGV;
            if (v > v1) { v2 = v1; i2 = i1; v1 = v; i1 = m + j; }
            else if (v > v2) { v2 = v; i2 = m + j; }
        }
    }
    for (int o = 16; o; o >>= 1) {
        float ov1 = __shfl_down_sync(0xffffffffu, v1, o);
        int   oi1 = __shfl_down_sync(0xffffffffu, i1, o);
        float ov2 = __shfl_down_sync(0xffffffffu, v2, o);
        int   oi2 = __shfl_down_sync(0xffffffffu, i2, o);
        ins2(ov1, oi1, v1, i1, v2, i2);
        ins2(ov2, oi2, v1, i1, v2, i2);
    }
    __shared__ float sv1[8], sv2[8];
    __shared__ int   si1[8], si2[8];
    if (lane == 0) { sv1[wid] = v1; si1[wid] = i1; sv2[wid] = v2; si2[wid] = i2; }
    __syncthreads();
    if (wid == 0) {
        if (lane < 8) { v1 = sv1[lane]; i1 = si1[lane]; v2 = sv2[lane]; i2 = si2[lane]; }
        else { v1 = v2 = -3.4e38f; i1 = i2 = 0x7fffffff; }
        for (int o = 4; o; o >>= 1) {
            float ov1 = __shfl_down_sync(0xffffffffu, v1, o);
            int   oi1 = __shfl_down_sync(0xffffffffu, i1, o);
            float ov2 = __shfl_down_sync(0xffffffffu, v2, o);
            int   oi2 = __shfl_down_sync(0xffffffffu, i2, o);
            ins2(ov1, oi1, v1, i1, v2, i2);
            ins2(ov2, oi2, v1, i1, v2, i2);
        }
        if (lane == 0) {
            g_wv[z][orig][0] = v1;
            g_wv[z][orig][1] = v2;
            g_wi[z][orig][0] = g_colidx[z][i1];
            g_wi[z][orig][1] = g_colidx[z][i2];
        }
    }
}

// ==================== means + softmax ====================
__global__ void weights_kernel(const float* __restrict__ mask) {
    const int n = threadIdx.x;
    const float f = mask[n];
    float s[5];
    s[0] = f;
    s[1] = g_wv[0][n][0] * f;
    s[2] = g_wv[0][n][1] * f;
    s[3] = g_wv[1][n][0] * f;
    s[4] = g_wv[1][n][1] * f;
    __shared__ float sm[5][32];
    __shared__ float tots[5];
    const int lane = n & 31, w = n >> 5;
    #pragma unroll
    for (int k = 0; k < 5; k++) {
        float v = s[k];
        for (int off = 16; off; off >>= 1) v += __shfl_down_sync(0xffffffffu, v, off);
        if (lane == 0) sm[k][w] = v;
    }
    __syncthreads();
    if (w < 5) {
        float v = sm[w][lane];
        for (int off = 16; off; off >>= 1) v += __shfl_down_sync(0xffffffffu, v, off);
        if (lane == 0) tots[w] = v;
    }
    __syncthreads();
    if (n == 0) {
        const float nm = tots[0];
        float mean[4];
        #pragma unroll
        for (int j = 0; j < 4; j++) mean[j] = tots[j + 1] / nm;
        float mx = mean[0];
        #pragma unroll
        for (int j = 1; j < 4; j++) mx = fmaxf(mx, mean[j]);
        float e[4], se = 0.f;
        #pragma unroll
        for (int j = 0; j < 4; j++) { e[j] = expf(mean[j] - mx); se += e[j]; }
        #pragma unroll
        for (int j = 0; j < 4; j++) g_weights[j] = e[j] / se;
    }
}

// ==================== gather: 8 channels per block ====================
__global__ __launch_bounds__(1024) void gather_kernel(const float* __restrict__ G,
                                                      const float* __restrict__ Kn,
                                                      const float* __restrict__ mask,
                                                      float* __restrict__ out) {
    const int c0 = blockIdx.x * 8;
    const int n = threadIdx.x;
    const float w0 = g_weights[0], w1 = g_weights[1], w2 = g_weights[2], w3 = g_weights[3];
    const float f = mask[n];
    const int a0 = g_wi[0][n][0], a1 = g_wi[0][n][1];
    const int b0 = g_wi[1][n][0], b1 = g_wi[1][n][1];
    const bool msk = (f == 1.0f);
    #pragma unroll
    for (int ch = 0; ch < 8; ch++) {
        const int c = c0 + ch;
        const float* __restrict__ kr = Kn + (size_t)c * NP;
        const float* __restrict__ gr = G  + (size_t)c * NP;
        float acc = 0.f;
        if (msk)
            acc = w0 * kr[a0] + w1 * kr[a1] + w2 * gr[b0] + w3 * gr[b1];
        if (n == 0) {
            const float kv = kr[0], gv = gr[0];
            acc += ((msk && a0 == 0) ? 0.f : w0) * kv
                 + ((msk && a1 == 0) ? 0.f : w1) * kv
                 + ((msk && b0 == 0) ? 0.f : w2) * gv
                 + ((msk && b1 == 0) ? 0.f : w3) * gv;
        }
        out[(size_t)(2 * CC + c) * NP + n] = acc;
    }
}

// ==================== launch ====================
extern "C" void kernel_launch(void* const* d_in, const int* in_sizes, int n_in,
                              void* d_out, int out_size) {
    const float* G    = (const float*)d_in[0];
    const float* Kn   = (const float*)d_in[1];
    const float* mask = (const float*)d_in[2];
    float* out = (float*)d_out;

    cudaFuncSetAttribute(gemm_tc, cudaFuncAttributeMaxDynamicSharedMemorySize, GEMM_SMEM);

    compact_kernel<<<1, 1024>>>(mask);
    split_kernel<<<dim3(16, KSLICES, 2), 256>>>(G, Kn);
    normr_kernel<<<2, 1024>>>();
    gemm_tc<<<dim3(16, 72, 2), 256, GEMM_SMEM>>>(G, Kn, out);  // y>=64 -> passthrough copy CTAs
    top2_kernel<<<2048, 256>>>();
    weights_kernel<<<1, 1024>>>(mask);
    gather_kernel<<<512, 1024>>>(G, Kn, mask, out);
}